// round 8
// baseline (speedup 1.0000x reference)
#include <cuda_runtime.h>
#include <cuda_bf16.h>
#include <cuda_fp16.h>
#include <cstdint>

// ---------------------------------------------------------------------------
#define BATCH 64
#define SEQ   1024
#define EDIM  256
#define HDIM  256
#define MTOT  (BATCH * SEQ)       // 65536

// Pre-split operands, produced once, consumed by MMA mainloops.
__device__ __nv_bfloat16 g_xh [(size_t)MTOT * EDIM];
__device__ __nv_bfloat16 g_xl [(size_t)MTOT * EDIM];
__device__ __nv_bfloat16 g_qh [(size_t)MTOT * HDIM];
__device__ __nv_bfloat16 g_ql [(size_t)MTOT * HDIM];
__device__ __nv_bfloat16 g_kh [(size_t)MTOT * HDIM];
__device__ __nv_bfloat16 g_kl [(size_t)MTOT * HDIM];
__device__ __half        g_vth[(size_t)BATCH * EDIM * SEQ];   // V^T fp16 (single)
__device__ float         g_s  [(size_t)BATCH * SEQ * SEQ];    // fp32 logits
__device__ __nv_bfloat16 g_wqTh[EDIM * HDIM], g_wqTl[EDIM * HDIM];
__device__ __nv_bfloat16 g_wkTh[EDIM * HDIM], g_wkTl[EDIM * HDIM];
__device__ __nv_bfloat16 g_wvTh[EDIM * HDIM], g_wvTl[EDIM * HDIM];

// ---------------------------------------------------------------------------
// helpers
// ---------------------------------------------------------------------------
__device__ __forceinline__ uint32_t smem_u32(const void* p) {
    uint32_t a;
    asm("{ .reg .u64 t; cvta.to.shared.u64 t, %1; cvt.u32.u64 %0, t; }" : "=r"(a) : "l"(p));
    return a;
}
__device__ __forceinline__ void ldsm_x4(uint32_t* r, uint32_t addr) {
    asm volatile("ldmatrix.sync.aligned.m8n8.x4.shared.b16 {%0,%1,%2,%3}, [%4];"
                 : "=r"(r[0]), "=r"(r[1]), "=r"(r[2]), "=r"(r[3]) : "r"(addr));
}
__device__ __forceinline__ void mma_bf16(float* c, const uint32_t* a, const uint32_t* b) {
    asm volatile(
        "mma.sync.aligned.m16n8k16.row.col.f32.bf16.bf16.f32 "
        "{%0,%1,%2,%3}, {%4,%5,%6,%7}, {%8,%9}, {%0,%1,%2,%3};"
        : "+f"(c[0]), "+f"(c[1]), "+f"(c[2]), "+f"(c[3])
        : "r"(a[0]), "r"(a[1]), "r"(a[2]), "r"(a[3]), "r"(b[0]), "r"(b[1]));
}
__device__ __forceinline__ void mma_f16(float* c, const uint32_t* a, const uint32_t* b) {
    asm volatile(
        "mma.sync.aligned.m16n8k16.row.col.f32.f16.f16.f32 "
        "{%0,%1,%2,%3}, {%4,%5,%6,%7}, {%8,%9}, {%0,%1,%2,%3};"
        : "+f"(c[0]), "+f"(c[1]), "+f"(c[2]), "+f"(c[3])
        : "r"(a[0]), "r"(a[1]), "r"(a[2]), "r"(a[3]), "r"(b[0]), "r"(b[1]));
}
// hi/lo bf16 split of two floats, packed as bf16x2 words
__device__ __forceinline__ void split2(float x, float y, uint32_t& h, uint32_t& l) {
    __nv_bfloat162 H = __floats2bfloat162_rn(x, y);
    float hx = __bfloat162float(__low2bfloat16(H));
    float hy = __bfloat162float(__high2bfloat16(H));
    __nv_bfloat162 L = __floats2bfloat162_rn(x - hx, y - hy);
    h = *reinterpret_cast<uint32_t*>(&H);
    l = *reinterpret_cast<uint32_t*>(&L);
}

#define CP16(sm, gp)  asm volatile("cp.async.cg.shared.global [%0], [%1], 16;" :: "r"(sm), "l"(gp))
#define CP_COMMIT()   asm volatile("cp.async.commit_group;" ::: "memory")
#define CP_WAIT1()    asm volatile("cp.async.wait_group 1;" ::: "memory")

// ---------------------------------------------------------------------------
// GEMM: C[128 x 256] = A[128 x K] @ B[256 x K]^T, 3-term bf16 (A,B hi/lo).
// 512 threads, 16 warps (4m x 4n), warp tile 32x64.
// K in chunks of 32; 3-stage cp.async pipeline, ONE __syncthreads per chunk.
// ---------------------------------------------------------------------------
#define ROWB   80
#define S_AH   0
#define S_AL   10240                 // 128*80
#define S_BH   20480
#define S_BL   40960                 // + 256*80
#define STAGE_SZ 61440
#define SMEM_SZ  (3 * STAGE_SZ)      // 184320

enum { M_PROJQK = 0, M_PROJVT = 1, M_QK = 2 };

template<int MODE, int NCHUNK>
__global__ __launch_bounds__(512, 1)
void gemm3(const float* __restrict__ bq, const float* __restrict__ bk,
           const float* __restrict__ bv, float* __restrict__ outp)
{
    extern __shared__ __align__(128) char smem[];
    const uint32_t sbase = smem_u32(smem);
    const int t    = threadIdx.x;
    const int lane = t & 31;
    const int wid  = t >> 5;          // 0..15
    const int wm   = wid >> 2;        // 0..3  (32-row slab)
    const int wn   = wid & 3;         // 0..3  (64-col slab)

    // ---- operand resolution ----
    const uint16_t *Ah, *Al, *Bh, *Bl;
    __nv_bfloat16 *Ch = nullptr, *Cl = nullptr;
    __half *Chh = nullptr;
    float* Cf = nullptr;
    const float* bias = nullptr;
    size_t lda, ldb, ldc;

    if (MODE == M_PROJQK) {
        int mt = blockIdx.x, qk = blockIdx.y;
        Ah = (const uint16_t*)(g_xh + (size_t)mt * 128 * EDIM);
        Al = (const uint16_t*)(g_xl + (size_t)mt * 128 * EDIM);                     lda = EDIM;
        Bh = (const uint16_t*)(qk ? g_wkTh : g_wqTh);
        Bl = (const uint16_t*)(qk ? g_wkTl : g_wqTl);                               ldb = EDIM;
        size_t co = (size_t)mt * 128 * HDIM;
        Ch = (qk ? g_kh : g_qh) + co;  Cl = (qk ? g_kl : g_ql) + co;                ldc = HDIM;
        bias = qk ? bk : bq;
    } else if (MODE == M_PROJVT) {
        int mt = blockIdx.x, nt = blockIdx.y, b = blockIdx.z;
        Ah = (const uint16_t*)(g_wvTh + (size_t)mt * 128 * EDIM);
        Al = (const uint16_t*)(g_wvTl + (size_t)mt * 128 * EDIM);                   lda = EDIM;
        size_t bo = ((size_t)b * SEQ + nt * 256) * EDIM;
        Bh = (const uint16_t*)(g_xh + bo);  Bl = (const uint16_t*)(g_xl + bo);      ldb = EDIM;
        Chh = g_vth + (size_t)b * EDIM * SEQ + (size_t)mt * 128 * SEQ + nt * 256;   ldc = SEQ;
        bias = bv + mt * 128;
    } else { // M_QK
        int mt = blockIdx.x, nt = blockIdx.y, b = blockIdx.z;
        size_t ao = ((size_t)b * SEQ + mt * 128) * HDIM;
        size_t bo = ((size_t)b * SEQ + nt * 256) * HDIM;
        Ah = (const uint16_t*)(g_qh + ao); Al = (const uint16_t*)(g_ql + ao);       lda = HDIM;
        Bh = (const uint16_t*)(g_kh + bo); Bl = (const uint16_t*)(g_kl + bo);       ldb = HDIM;
        Cf = g_s + (size_t)b * SEQ * SEQ + (size_t)mt * 128 * SEQ + nt * 256;       ldc = SEQ;
    }

    float acc[2][8][4];
#pragma unroll
    for (int i = 0; i < 2; i++)
#pragma unroll
        for (int j = 0; j < 8; j++)
#pragma unroll
            for (int e = 0; e < 4; e++) acc[i][j][e] = 0.f;

    // cp.async mapping: A 128 rows x 64B, B 256 rows x 64B, 16B per txn.
    const int r_ld = t >> 2;             // 0..127
    const int cb16 = (t & 3) << 4;       // smem byte within row
    const int cel  = (t & 3) << 3;       // gmem element offset

#define LOAD_STAGE(J, BUF)                                                     \
    {                                                                          \
        const uint32_t sp = sbase + (uint32_t)(BUF) * STAGE_SZ;                \
        uint32_t soA = (uint32_t)(r_ld * ROWB + cb16);                         \
        size_t gaA = (size_t)r_ld * lda + (size_t)(J) * 32 + cel;              \
        CP16(sp + S_AH + soA, Ah + gaA);                                       \
        CP16(sp + S_AL + soA, Al + gaA);                                       \
        _Pragma("unroll")                                                      \
        for (int i = 0; i < 2; i++) {                                          \
            int r = r_ld + 128 * i;                                            \
            uint32_t so = (uint32_t)(r * ROWB + cb16);                         \
            size_t gb = (size_t)r * ldb + (size_t)(J) * 32 + cel;              \
            CP16(sp + S_BH + so, Bh + gb);                                     \
            CP16(sp + S_BL + so, Bl + gb);                                     \
        }                                                                      \
    }

    // ldmatrix offsets (within region)
    const uint32_t aoff = (uint32_t)((wm * 32 + (lane & 15)) * ROWB + ((lane >> 4) << 4));
    const uint32_t boff = (uint32_t)((wn * 64 + ((lane >> 4) << 3) + (lane & 7)) * ROWB
                                     + (((lane >> 3) & 1) << 4));

    // prologue: 2 stages in flight
    LOAD_STAGE(0, 0); CP_COMMIT();
    LOAD_STAGE(1, 1); CP_COMMIT();

#pragma unroll 1
    for (int j = 0; j < NCHUNK; j++) {
        CP_WAIT1();
        __syncthreads();    // single barrier per chunk

        const uint32_t st = sbase + (uint32_t)(j % 3) * STAGE_SZ;
#pragma unroll
        for (int ks = 0; ks < 2; ks++) {
            const uint32_t ko = (uint32_t)(ks * 32);
            uint32_t ah[2][4], al[2][4], b4[4][4];
#pragma unroll
            for (int mf = 0; mf < 2; mf++) {
                uint32_t a = st + aoff + (uint32_t)(mf * 16 * ROWB) + ko;
                ldsm_x4(ah[mf], a + S_AH);
                ldsm_x4(al[mf], a + S_AL);
            }
#pragma unroll
            for (int ng = 0; ng < 4; ng++)
                ldsm_x4(b4[ng], st + S_BH + boff + (uint32_t)(ng * 16 * ROWB) + ko);
#pragma unroll
            for (int mf = 0; mf < 2; mf++)
#pragma unroll
                for (int nf = 0; nf < 8; nf++)
                    mma_bf16(acc[mf][nf], ah[mf], &b4[nf >> 1][(nf & 1) * 2]);
#pragma unroll
            for (int mf = 0; mf < 2; mf++)
#pragma unroll
                for (int nf = 0; nf < 8; nf++)
                    mma_bf16(acc[mf][nf], al[mf], &b4[nf >> 1][(nf & 1) * 2]);
            // reload B regs with lo halves
#pragma unroll
            for (int ng = 0; ng < 4; ng++)
                ldsm_x4(b4[ng], st + S_BL + boff + (uint32_t)(ng * 16 * ROWB) + ko);
#pragma unroll
            for (int mf = 0; mf < 2; mf++)
#pragma unroll
                for (int nf = 0; nf < 8; nf++)
                    mma_bf16(acc[mf][nf], ah[mf], &b4[nf >> 1][(nf & 1) * 2]);

            if (ks == 0) {   // issue next-stage loads between the two k-steps
                if (j + 2 < NCHUNK) LOAD_STAGE(j + 2, (j + 2) % 3);
                CP_COMMIT();
            }
        }
    }

    // ---- epilogue ----
#pragma unroll
    for (int mf = 0; mf < 2; mf++) {
        const int r0 = wm * 32 + mf * 16 + (lane >> 2);
        const int r1 = r0 + 8;
#pragma unroll
        for (int nf = 0; nf < 8; nf++) {
            const int c = wn * 64 + nf * 8 + ((lane & 3) << 1);
            float* a = acc[mf][nf];
            if (MODE == M_PROJQK) {
                float cb0 = bias[c], cb1 = bias[c + 1];
                uint32_t h, l;
                split2(a[0] + cb0, a[1] + cb1, h, l);
                *(uint32_t*)(Ch + (size_t)r0 * ldc + c) = h;
                *(uint32_t*)(Cl + (size_t)r0 * ldc + c) = l;
                split2(a[2] + cb0, a[3] + cb1, h, l);
                *(uint32_t*)(Ch + (size_t)r1 * ldc + c) = h;
                *(uint32_t*)(Cl + (size_t)r1 * ldc + c) = l;
            } else if (MODE == M_PROJVT) {
                float rb0 = bias[r0], rb1 = bias[r1];
                __half2 h0 = __floats2half2_rn(a[0] + rb0, a[1] + rb0);
                __half2 h1 = __floats2half2_rn(a[2] + rb1, a[3] + rb1);
                *(uint32_t*)(Chh + (size_t)r0 * ldc + c) = *reinterpret_cast<uint32_t*>(&h0);
                *(uint32_t*)(Chh + (size_t)r1 * ldc + c) = *reinterpret_cast<uint32_t*>(&h1);
            } else {
                *(float2*)(Cf + (size_t)r0 * ldc + c) = make_float2(a[0], a[1]);
                *(float2*)(Cf + (size_t)r1 * ldc + c) = make_float2(a[2], a[3]);
            }
        }
    }
#undef LOAD_STAGE
}

// ---------------------------------------------------------------------------
// Fused softmax + PV: one CTA per (128 q rows, batch).
// Pass 1: stream fp32 logit rows twice (max, sum-exp), stats in smem.
// Mainloop: P = exp(s - m) computed in regs -> fp16 smem (double buf);
//           V^T fp16 streamed by cp.async (3 stages); 1-term fp16 MMA.
// Epilogue: O * (1/l).
// ---------------------------------------------------------------------------
#define PV_PBUF   10240                  // 128 rows * 80B
#define PV_SPV    20480                  // after 2 P buffers
#define PV_VSTG   20480                  // 256 rows * 80B
#define PV_STAT   (PV_SPV + 3 * PV_VSTG) // 81920
#define PV_SMEM   (PV_STAT + 4096)       // 86016

__global__ __launch_bounds__(512, 1)
void attn_pv(float* __restrict__ outp)
{
    extern __shared__ __align__(128) char smem[];
    const uint32_t sbase = smem_u32(smem);
    float* smax = (float*)(smem + PV_STAT);
    float* ssum = (float*)(smem + PV_STAT + 2048);

    const int t    = threadIdx.x;
    const int lane = t & 31;
    const int wid  = t >> 5;
    const int wm   = wid >> 2;
    const int wn   = wid & 3;
    const int mt   = blockIdx.x;
    const int b    = blockIdx.y;

    const float*  Sp = g_s + (size_t)b * SEQ * SEQ + (size_t)mt * 128 * SEQ;
    const __half* Vt = g_vth + (size_t)b * EDIM * SEQ;
    float*        Op = outp + ((size_t)b * SEQ + mt * 128) * EDIM;

    // ---- V cp.async prologue (independent of pass 1) ----
    const int vr = t >> 1;
    const int vc = t & 1;
#define LOAD_V(J, BUF)                                                         \
    {                                                                          \
        uint32_t so = sbase + PV_SPV + (uint32_t)(BUF) * PV_VSTG               \
                      + (uint32_t)(vr * ROWB + vc * 32);                       \
        const __half* gv = Vt + (size_t)vr * SEQ + (J) * 32 + vc * 16;         \
        CP16(so, gv); CP16(so + 16, gv + 8);                                   \
    }
    LOAD_V(0, 0); CP_COMMIT();
    LOAD_V(1, 1); CP_COMMIT();

    // ---- pass 1: per-row max and sum of exp ----
    const int prow = t >> 2;       // 0..127
    const int psub = t & 3;        // 256-col strip
    const float4* srow = (const float4*)(Sp + (size_t)prow * SEQ + psub * 256);
    float m = -3.4e38f;
#pragma unroll 8
    for (int i = 0; i < 64; i++) {
        float4 v = srow[i];
        m = fmaxf(m, fmaxf(fmaxf(v.x, v.y), fmaxf(v.z, v.w)));
    }
    smax[prow * 4 + psub] = m;
    __syncthreads();
    const float rm = fmaxf(fmaxf(smax[prow * 4 + 0], smax[prow * 4 + 1]),
                           fmaxf(smax[prow * 4 + 2], smax[prow * 4 + 3]));
    float sum = 0.f;
#pragma unroll 8
    for (int i = 0; i < 64; i++) {
        float4 v = srow[i];
        sum += __expf(v.x - rm) + __expf(v.y - rm)
             + __expf(v.z - rm) + __expf(v.w - rm);
    }
    ssum[prow * 4 + psub] = sum;     // consumed after loop (syncs inside loop)

    float acc[2][8][4];
#pragma unroll
    for (int i = 0; i < 2; i++)
#pragma unroll
        for (int j = 0; j < 8; j++)
#pragma unroll
            for (int e = 0; e < 4; e++) acc[i][j][e] = 0.f;

    // P chunk compute/store: thread -> (row prow, 8 keys at (t&3)*8)
    const float* sc = Sp + (size_t)prow * SEQ + (t & 3) * 8;
#define STORE_P(BUF, A, B2)                                                    \
    {                                                                          \
        __half2 h0 = __floats2half2_rn(__expf((A).x - rm), __expf((A).y - rm));\
        __half2 h1 = __floats2half2_rn(__expf((A).z - rm), __expf((A).w - rm));\
        __half2 h2 = __floats2half2_rn(__expf((B2).x - rm), __expf((B2).y - rm));\
        __half2 h3 = __floats2half2_rn(__expf((B2).z - rm), __expf((B2).w - rm));\
        uint4 u;                                                               \
        u.x = *reinterpret_cast<uint32_t*>(&h0);                               \
        u.y = *reinterpret_cast<uint32_t*>(&h1);                               \
        u.z = *reinterpret_cast<uint32_t*>(&h2);                               \
        u.w = *reinterpret_cast<uint32_t*>(&h3);                               \
        *(uint4*)(smem + (BUF) * PV_PBUF + prow * ROWB + (t & 3) * 16) = u;    \
    }
    {
        float4 s0 = *(const float4*)(sc);
        float4 s1 = *(const float4*)(sc + 4);
        STORE_P(0, s0, s1);
    }

    const uint32_t aoffp = (uint32_t)((wm * 32 + (lane & 15)) * ROWB + ((lane >> 4) << 4));
    const uint32_t boff  = (uint32_t)((wn * 64 + ((lane >> 4) << 3) + (lane & 7)) * ROWB
                                      + (((lane >> 3) & 1) << 4));

#pragma unroll 1
    for (int j = 0; j < 32; j++) {
        CP_WAIT1();
        __syncthreads();   // V[j] staged; P[j] stores visible

        // prefetch s for chunk j+1
        float4 sn0, sn1;
        if (j + 1 < 32) {
            sn0 = *(const float4*)(sc + (j + 1) * 32);
            sn1 = *(const float4*)(sc + (j + 1) * 32 + 4);
        }

        const uint32_t stv = sbase + PV_SPV + (uint32_t)(j % 3) * PV_VSTG;
        const uint32_t stp = sbase + (uint32_t)(j & 1) * PV_PBUF;
#pragma unroll
        for (int ks = 0; ks < 2; ks++) {
            const uint32_t ko = (uint32_t)(ks * 32);
            uint32_t ah[2][4], b4[4][4];
#pragma unroll
            for (int mf = 0; mf < 2; mf++)
                ldsm_x4(ah[mf], stp + aoffp + (uint32_t)(mf * 16 * ROWB) + ko);
#pragma unroll
            for (int ng = 0; ng < 4; ng++)
                ldsm_x4(b4[ng], stv + boff + (uint32_t)(ng * 16 * ROWB) + ko);
#pragma unroll
            for (int mf = 0; mf < 2; mf++)
#pragma unroll
                for (int nf = 0; nf < 8; nf++)
                    mma_f16(acc[mf][nf], ah[mf], &b4[nf >> 1][(nf & 1) * 2]);

            if (ks == 0) {
                if (j + 2 < 32) LOAD_V(j + 2, (j + 2) % 3);
                CP_COMMIT();
            }
        }

        if (j + 1 < 32) STORE_P((j + 1) & 1, sn0, sn1);
    }

    // ---- epilogue: scale by 1/l ----
#pragma unroll
    for (int mf = 0; mf < 2; mf++) {
        const int r0 = wm * 32 + mf * 16 + (lane >> 2);
        const int r1 = r0 + 8;
        const float inv0 = 1.f / (ssum[r0 * 4] + ssum[r0 * 4 + 1] + ssum[r0 * 4 + 2] + ssum[r0 * 4 + 3]);
        const float inv1 = 1.f / (ssum[r1 * 4] + ssum[r1 * 4 + 1] + ssum[r1 * 4 + 2] + ssum[r1 * 4 + 3]);
#pragma unroll
        for (int nf = 0; nf < 8; nf++) {
            const int c = wn * 64 + nf * 8 + ((lane & 3) << 1);
            float* a = acc[mf][nf];
            *(float2*)(Op + (size_t)r0 * EDIM + c) = make_float2(a[0] * inv0, a[1] * inv0);
            *(float2*)(Op + (size_t)r1 * EDIM + c) = make_float2(a[2] * inv1, a[3] * inv1);
        }
    }
#undef LOAD_V
#undef STORE_P
}

// ---------------------------------------------------------------------------
// Prep: split x into bf16 hi/lo
// ---------------------------------------------------------------------------
__global__ __launch_bounds__(256) void split_x(const float* __restrict__ x)
{
    size_t i = ((size_t)blockIdx.x * 256 + threadIdx.x) * 4;
    float4 v = *(const float4*)(x + i);
    uint32_t h01, l01, h23, l23;
    split2(v.x, v.y, h01, l01);
    split2(v.z, v.w, h23, l23);
    *(uint2*)(g_xh + i) = make_uint2(h01, h23);
    *(uint2*)(g_xl + i) = make_uint2(l01, l23);
}

// ---------------------------------------------------------------------------
// Prep: transpose W and split into bf16 hi/lo
// ---------------------------------------------------------------------------
__global__ __launch_bounds__(256) void transpose_split_w(const float* __restrict__ Wq,
                                                         const float* __restrict__ Wk,
                                                         const float* __restrict__ Wv)
{
    const float* src = (blockIdx.x == 0) ? Wq : (blockIdx.x == 1) ? Wk : Wv;
    __nv_bfloat16* dh = (blockIdx.x == 0) ? g_wqTh : (blockIdx.x == 1) ? g_wkTh : g_wvTh;
    __nv_bfloat16* dl = (blockIdx.x == 0) ? g_wqTl : (blockIdx.x == 1) ? g_wkTl : g_wvTl;
    __shared__ float sm[32 * 33];
    int w = threadIdx.x >> 5, l = threadIdx.x & 31;
    for (int ti = 0; ti < 8; ti++)
        for (int tj = 0; tj < 8; tj++) {
#pragma unroll
            for (int k = 0; k < 4; k++) {
                int r = w * 4 + k;
                sm[r * 33 + l] = src[(size_t)(ti * 32 + r) * 256 + tj * 32 + l];
            }
            __syncthreads();
#pragma unroll
            for (int k = 0; k < 4; k++) {
                int r = w * 4 + k;
                float v = sm[l * 33 + r];
                __nv_bfloat16 h = __float2bfloat16_rn(v);
                float hv = __bfloat162float(h);
                dh[(size_t)(tj * 32 + r) * 256 + ti * 32 + l] = h;
                dl[(size_t)(tj * 32 + r) * 256 + ti * 32 + l] = __float2bfloat16_rn(v - hv);
            }
            __syncthreads();
        }
}

// ---------------------------------------------------------------------------
extern "C" void kernel_launch(void* const* d_in, const int* in_sizes, int n_in,
                              void* d_out, int out_size)
{
    const float* x  = (const float*)d_in[0];
    const float* Wq = (const float*)d_in[1];
    const float* bq = (const float*)d_in[2];
    const float* Wk = (const float*)d_in[3];
    const float* bk = (const float*)d_in[4];
    const float* Wv = (const float*)d_in[5];
    const float* bv = (const float*)d_in[6];
    float* out = (float*)d_out;

    cudaFuncSetAttribute(gemm3<M_PROJQK, 8>, cudaFuncAttributeMaxDynamicSharedMemorySize, SMEM_SZ);
    cudaFuncSetAttribute(gemm3<M_PROJVT, 8>, cudaFuncAttributeMaxDynamicSharedMemorySize, SMEM_SZ);
    cudaFuncSetAttribute(gemm3<M_QK, 8>,     cudaFuncAttributeMaxDynamicSharedMemorySize, SMEM_SZ);
    cudaFuncSetAttribute(attn_pv,            cudaFuncAttributeMaxDynamicSharedMemorySize, PV_SMEM);

    split_x<<<(MTOT * EDIM) / 1024, 256>>>(x);
    transpose_split_w<<<3, 256>>>(Wq, Wk, Wv);

    gemm3<M_PROJQK, 8><<<dim3(MTOT / 128, 2),    512, SMEM_SZ>>>(bq, bk, bv, out);
    gemm3<M_PROJVT, 8><<<dim3(2, 4, BATCH),      512, SMEM_SZ>>>(bq, bk, bv, out);
    gemm3<M_QK, 8>    <<<dim3(8, 4, BATCH),      512, SMEM_SZ>>>(bq, bk, bv, out);
    attn_pv           <<<dim3(8, BATCH),         512, PV_SMEM>>>(out);
}

// round 9
// speedup vs baseline: 1.1134x; 1.1134x over previous
#include <cuda_runtime.h>
#include <cuda_bf16.h>
#include <cuda_fp16.h>
#include <cstdint>

// ---------------------------------------------------------------------------
#define BATCH 64
#define SEQ   1024
#define EDIM  256
#define HDIM  256
#define MTOT  (BATCH * SEQ)       // 65536

// Pre-split operands, produced once, consumed by MMA mainloops.
__device__ __nv_bfloat16 g_xh [(size_t)MTOT * EDIM];
__device__ __nv_bfloat16 g_xl [(size_t)MTOT * EDIM];
__device__ __nv_bfloat16 g_qh [(size_t)MTOT * HDIM];
__device__ __nv_bfloat16 g_ql [(size_t)MTOT * HDIM];
__device__ __nv_bfloat16 g_kh [(size_t)MTOT * HDIM];
__device__ __nv_bfloat16 g_kl [(size_t)MTOT * HDIM];
__device__ __half        g_vth[(size_t)BATCH * EDIM * SEQ];   // V^T fp16 (single)
__device__ __half        g_ph [(size_t)BATCH * SEQ * SEQ];    // P fp16 (single)
__device__ float         g_s  [(size_t)BATCH * SEQ * SEQ];    // fp32 logits
__device__ __nv_bfloat16 g_wqTh[EDIM * HDIM], g_wqTl[EDIM * HDIM];
__device__ __nv_bfloat16 g_wkTh[EDIM * HDIM], g_wkTl[EDIM * HDIM];
__device__ __nv_bfloat16 g_wvTh[EDIM * HDIM], g_wvTl[EDIM * HDIM];

// ---------------------------------------------------------------------------
// helpers
// ---------------------------------------------------------------------------
__device__ __forceinline__ uint32_t smem_u32(const void* p) {
    uint32_t a;
    asm("{ .reg .u64 t; cvta.to.shared.u64 t, %1; cvt.u32.u64 %0, t; }" : "=r"(a) : "l"(p));
    return a;
}
__device__ __forceinline__ void ldsm_x4(uint32_t* r, uint32_t addr) {
    asm volatile("ldmatrix.sync.aligned.m8n8.x4.shared.b16 {%0,%1,%2,%3}, [%4];"
                 : "=r"(r[0]), "=r"(r[1]), "=r"(r[2]), "=r"(r[3]) : "r"(addr));
}
__device__ __forceinline__ void mma_bf16(float* c, const uint32_t* a, const uint32_t* b) {
    asm volatile(
        "mma.sync.aligned.m16n8k16.row.col.f32.bf16.bf16.f32 "
        "{%0,%1,%2,%3}, {%4,%5,%6,%7}, {%8,%9}, {%0,%1,%2,%3};"
        : "+f"(c[0]), "+f"(c[1]), "+f"(c[2]), "+f"(c[3])
        : "r"(a[0]), "r"(a[1]), "r"(a[2]), "r"(a[3]), "r"(b[0]), "r"(b[1]));
}
__device__ __forceinline__ void mma_f16(float* c, const uint32_t* a, const uint32_t* b) {
    asm volatile(
        "mma.sync.aligned.m16n8k16.row.col.f32.f16.f16.f32 "
        "{%0,%1,%2,%3}, {%4,%5,%6,%7}, {%8,%9}, {%0,%1,%2,%3};"
        : "+f"(c[0]), "+f"(c[1]), "+f"(c[2]), "+f"(c[3])
        : "r"(a[0]), "r"(a[1]), "r"(a[2]), "r"(a[3]), "r"(b[0]), "r"(b[1]));
}
// hi/lo bf16 split of two floats, packed as bf16x2 words
__device__ __forceinline__ void split2(float x, float y, uint32_t& h, uint32_t& l) {
    __nv_bfloat162 H = __floats2bfloat162_rn(x, y);
    float hx = __bfloat162float(__low2bfloat16(H));
    float hy = __bfloat162float(__high2bfloat16(H));
    __nv_bfloat162 L = __floats2bfloat162_rn(x - hx, y - hy);
    h = *reinterpret_cast<uint32_t*>(&H);
    l = *reinterpret_cast<uint32_t*>(&L);
}

#define CP16(sm, gp)  asm volatile("cp.async.cg.shared.global [%0], [%1], 16;" :: "r"(sm), "l"(gp))
#define CP_COMMIT()   asm volatile("cp.async.commit_group;" ::: "memory")
#define CP_WAIT1()    asm volatile("cp.async.wait_group 1;" ::: "memory")

// ---------------------------------------------------------------------------
// GEMM: C[128 x 256] = A[128 x K] @ B[256 x K]^T.
// 512 threads, 16 warps (4m x 4n), warp tile 32x64.
// K in chunks of 32; 3-stage cp.async pipeline, ONE __syncthreads per chunk.
// M_PV: 1-term fp16 (A = P fp16, B = V^T fp16). Others: 3-term bf16 hi/lo.
// ---------------------------------------------------------------------------
#define ROWB   80
#define S_AH   0
#define S_AL   10240                 // 128*80
#define S_BH   20480
#define S_BL   40960                 // + 256*80
#define STAGE_SZ 61440
#define SMEM_SZ  (3 * STAGE_SZ)      // 184320

enum { M_PROJQK = 0, M_PROJVT = 1, M_QK = 2, M_PV = 3 };

template<int MODE, int NCHUNK>
__global__ __launch_bounds__(512, 1)
void gemm3(const float* __restrict__ bq, const float* __restrict__ bk,
           const float* __restrict__ bv, float* __restrict__ outp)
{
    extern __shared__ __align__(128) char smem[];
    const uint32_t sbase = smem_u32(smem);
    const int t    = threadIdx.x;
    const int lane = t & 31;
    const int wid  = t >> 5;          // 0..15
    const int wm   = wid >> 2;        // 0..3  (32-row slab)
    const int wn   = wid & 3;         // 0..3  (64-col slab)

    // ---- operand resolution ----
    const uint16_t *Ah, *Al = nullptr, *Bh, *Bl = nullptr;
    __nv_bfloat16 *Ch = nullptr, *Cl = nullptr;
    __half *Chh = nullptr;
    float* Cf = nullptr;
    const float* bias = nullptr;
    size_t lda, ldb, ldc;

    if (MODE == M_PROJQK) {
        int mt = blockIdx.x, qk = blockIdx.y;
        Ah = (const uint16_t*)(g_xh + (size_t)mt * 128 * EDIM);
        Al = (const uint16_t*)(g_xl + (size_t)mt * 128 * EDIM);                     lda = EDIM;
        Bh = (const uint16_t*)(qk ? g_wkTh : g_wqTh);
        Bl = (const uint16_t*)(qk ? g_wkTl : g_wqTl);                               ldb = EDIM;
        size_t co = (size_t)mt * 128 * HDIM;
        Ch = (qk ? g_kh : g_qh) + co;  Cl = (qk ? g_kl : g_ql) + co;                ldc = HDIM;
        bias = qk ? bk : bq;
    } else if (MODE == M_PROJVT) {
        int mt = blockIdx.x, nt = blockIdx.y, b = blockIdx.z;
        Ah = (const uint16_t*)(g_wvTh + (size_t)mt * 128 * EDIM);
        Al = (const uint16_t*)(g_wvTl + (size_t)mt * 128 * EDIM);                   lda = EDIM;
        size_t bo = ((size_t)b * SEQ + nt * 256) * EDIM;
        Bh = (const uint16_t*)(g_xh + bo);  Bl = (const uint16_t*)(g_xl + bo);      ldb = EDIM;
        Chh = g_vth + (size_t)b * EDIM * SEQ + (size_t)mt * 128 * SEQ + nt * 256;   ldc = SEQ;
        bias = bv + mt * 128;
    } else if (MODE == M_QK) {
        int mt = blockIdx.x, nt = blockIdx.y, b = blockIdx.z;
        size_t ao = ((size_t)b * SEQ + mt * 128) * HDIM;
        size_t bo = ((size_t)b * SEQ + nt * 256) * HDIM;
        Ah = (const uint16_t*)(g_qh + ao); Al = (const uint16_t*)(g_ql + ao);       lda = HDIM;
        Bh = (const uint16_t*)(g_kh + bo); Bl = (const uint16_t*)(g_kl + bo);       ldb = HDIM;
        Cf = g_s + (size_t)b * SEQ * SEQ + (size_t)mt * 128 * SEQ + nt * 256;       ldc = SEQ;
    } else { // M_PV: 1-term fp16
        int mt = blockIdx.x, b = blockIdx.z;
        Ah = (const uint16_t*)(g_ph + (size_t)b * SEQ * SEQ + (size_t)mt * 128 * SEQ); lda = SEQ;
        Bh = (const uint16_t*)(g_vth + (size_t)b * EDIM * SEQ);                     ldb = SEQ;
        Cf = outp + ((size_t)b * SEQ + mt * 128) * EDIM;                            ldc = EDIM;
    }

    float acc[2][8][4];
#pragma unroll
    for (int i = 0; i < 2; i++)
#pragma unroll
        for (int j = 0; j < 8; j++)
#pragma unroll
            for (int e = 0; e < 4; e++) acc[i][j][e] = 0.f;

    // cp.async mapping: A 128 rows x 64B, B 256 rows x 64B, 16B per txn.
    const int r_ld = t >> 2;             // 0..127
    const int cb16 = (t & 3) << 4;       // smem byte within row
    const int cel  = (t & 3) << 3;       // gmem element offset

#define LOAD_STAGE(J, BUF)                                                     \
    {                                                                          \
        const uint32_t sp = sbase + (uint32_t)(BUF) * STAGE_SZ;                \
        uint32_t soA = (uint32_t)(r_ld * ROWB + cb16);                         \
        size_t gaA = (size_t)r_ld * lda + (size_t)(J) * 32 + cel;              \
        CP16(sp + S_AH + soA, Ah + gaA);                                       \
        if (MODE != M_PV) CP16(sp + S_AL + soA, Al + gaA);                     \
        _Pragma("unroll")                                                      \
        for (int i = 0; i < 2; i++) {                                          \
            int r = r_ld + 128 * i;                                            \
            uint32_t so = (uint32_t)(r * ROWB + cb16);                         \
            size_t gb = (size_t)r * ldb + (size_t)(J) * 32 + cel;              \
            CP16(sp + S_BH + so, Bh + gb);                                     \
            if (MODE != M_PV) CP16(sp + S_BL + so, Bl + gb);                   \
        }                                                                      \
    }

    // ldmatrix offsets (within region)
    const uint32_t aoff = (uint32_t)((wm * 32 + (lane & 15)) * ROWB + ((lane >> 4) << 4));
    const uint32_t boff = (uint32_t)((wn * 64 + ((lane >> 4) << 3) + (lane & 7)) * ROWB
                                     + (((lane >> 3) & 1) << 4));

    // prologue: 2 stages in flight
    LOAD_STAGE(0, 0); CP_COMMIT();
    LOAD_STAGE(1, 1); CP_COMMIT();

#pragma unroll 1
    for (int j = 0; j < NCHUNK; j++) {
        CP_WAIT1();
        __syncthreads();    // single barrier per chunk

        const uint32_t st = sbase + (uint32_t)(j % 3) * STAGE_SZ;
#pragma unroll
        for (int ks = 0; ks < 2; ks++) {
            const uint32_t ko = (uint32_t)(ks * 32);
            uint32_t ah[2][4], al[2][4], b4[4][4];
#pragma unroll
            for (int mf = 0; mf < 2; mf++) {
                uint32_t a = st + aoff + (uint32_t)(mf * 16 * ROWB) + ko;
                ldsm_x4(ah[mf], a + S_AH);
                if (MODE != M_PV) ldsm_x4(al[mf], a + S_AL);
            }
#pragma unroll
            for (int ng = 0; ng < 4; ng++)
                ldsm_x4(b4[ng], st + S_BH + boff + (uint32_t)(ng * 16 * ROWB) + ko);

            if (MODE == M_PV) {
#pragma unroll
                for (int mf = 0; mf < 2; mf++)
#pragma unroll
                    for (int nf = 0; nf < 8; nf++)
                        mma_f16(acc[mf][nf], ah[mf], &b4[nf >> 1][(nf & 1) * 2]);
            } else {
#pragma unroll
                for (int mf = 0; mf < 2; mf++)
#pragma unroll
                    for (int nf = 0; nf < 8; nf++)
                        mma_bf16(acc[mf][nf], ah[mf], &b4[nf >> 1][(nf & 1) * 2]);
#pragma unroll
                for (int mf = 0; mf < 2; mf++)
#pragma unroll
                    for (int nf = 0; nf < 8; nf++)
                        mma_bf16(acc[mf][nf], al[mf], &b4[nf >> 1][(nf & 1) * 2]);
                // reload B regs with lo halves
#pragma unroll
                for (int ng = 0; ng < 4; ng++)
                    ldsm_x4(b4[ng], st + S_BL + boff + (uint32_t)(ng * 16 * ROWB) + ko);
#pragma unroll
                for (int mf = 0; mf < 2; mf++)
#pragma unroll
                    for (int nf = 0; nf < 8; nf++)
                        mma_bf16(acc[mf][nf], ah[mf], &b4[nf >> 1][(nf & 1) * 2]);
            }

            if (ks == 0) {   // issue next-stage loads between the two k-steps
                if (j + 2 < NCHUNK) LOAD_STAGE(j + 2, (j + 2) % 3);
                CP_COMMIT();
            }
        }
    }

    // ---- epilogue ----
#pragma unroll
    for (int mf = 0; mf < 2; mf++) {
        const int r0 = wm * 32 + mf * 16 + (lane >> 2);
        const int r1 = r0 + 8;
#pragma unroll
        for (int nf = 0; nf < 8; nf++) {
            const int c = wn * 64 + nf * 8 + ((lane & 3) << 1);
            float* a = acc[mf][nf];
            if (MODE == M_PROJQK) {
                float cb0 = bias[c], cb1 = bias[c + 1];
                uint32_t h, l;
                split2(a[0] + cb0, a[1] + cb1, h, l);
                *(uint32_t*)(Ch + (size_t)r0 * ldc + c) = h;
                *(uint32_t*)(Cl + (size_t)r0 * ldc + c) = l;
                split2(a[2] + cb0, a[3] + cb1, h, l);
                *(uint32_t*)(Ch + (size_t)r1 * ldc + c) = h;
                *(uint32_t*)(Cl + (size_t)r1 * ldc + c) = l;
            } else if (MODE == M_PROJVT) {
                float rb0 = bias[r0], rb1 = bias[r1];
                __half2 h0 = __floats2half2_rn(a[0] + rb0, a[1] + rb0);
                __half2 h1 = __floats2half2_rn(a[2] + rb1, a[3] + rb1);
                *(uint32_t*)(Chh + (size_t)r0 * ldc + c) = *reinterpret_cast<uint32_t*>(&h0);
                *(uint32_t*)(Chh + (size_t)r1 * ldc + c) = *reinterpret_cast<uint32_t*>(&h1);
            } else {
                *(float2*)(Cf + (size_t)r0 * ldc + c) = make_float2(a[0], a[1]);
                *(float2*)(Cf + (size_t)r1 * ldc + c) = make_float2(a[2], a[3]);
            }
        }
    }
#undef LOAD_STAGE
}

// ---------------------------------------------------------------------------
// Prep: split x into bf16 hi/lo
// ---------------------------------------------------------------------------
__global__ __launch_bounds__(256) void split_x(const float* __restrict__ x)
{
    size_t i = ((size_t)blockIdx.x * 256 + threadIdx.x) * 4;
    float4 v = *(const float4*)(x + i);
    uint32_t h01, l01, h23, l23;
    split2(v.x, v.y, h01, l01);
    split2(v.z, v.w, h23, l23);
    *(uint2*)(g_xh + i) = make_uint2(h01, h23);
    *(uint2*)(g_xl + i) = make_uint2(l01, l23);
}

// ---------------------------------------------------------------------------
// Prep: transpose W and split into bf16 hi/lo
// ---------------------------------------------------------------------------
__global__ __launch_bounds__(256) void transpose_split_w(const float* __restrict__ Wq,
                                                         const float* __restrict__ Wk,
                                                         const float* __restrict__ Wv)
{
    const float* src = (blockIdx.x == 0) ? Wq : (blockIdx.x == 1) ? Wk : Wv;
    __nv_bfloat16* dh = (blockIdx.x == 0) ? g_wqTh : (blockIdx.x == 1) ? g_wkTh : g_wvTh;
    __nv_bfloat16* dl = (blockIdx.x == 0) ? g_wqTl : (blockIdx.x == 1) ? g_wkTl : g_wvTl;
    __shared__ float sm[32 * 33];
    int w = threadIdx.x >> 5, l = threadIdx.x & 31;
    for (int ti = 0; ti < 8; ti++)
        for (int tj = 0; tj < 8; tj++) {
#pragma unroll
            for (int k = 0; k < 4; k++) {
                int r = w * 4 + k;
                sm[r * 33 + l] = src[(size_t)(ti * 32 + r) * 256 + tj * 32 + l];
            }
            __syncthreads();
#pragma unroll
            for (int k = 0; k < 4; k++) {
                int r = w * 4 + k;
                float v = sm[l * 33 + r];
                __nv_bfloat16 h = __float2bfloat16_rn(v);
                float hv = __bfloat162float(h);
                dh[(size_t)(tj * 32 + r) * 256 + ti * 32 + l] = h;
                dl[(size_t)(tj * 32 + r) * 256 + ti * 32 + l] = __float2bfloat16_rn(v - hv);
            }
            __syncthreads();
        }
}

// ---------------------------------------------------------------------------
// Softmax: one warp per row; reads fp32 logits, writes P as fp16 (single)
// ---------------------------------------------------------------------------
__global__ __launch_bounds__(256) void softmax_rows()
{
    const size_t row = (size_t)blockIdx.x * 8 + (threadIdx.x >> 5);
    const int l = threadIdx.x & 31;
    const float4* p = (const float4*)(g_s + row * SEQ);

    float4 v[8];
    float mx = -3.4e38f;
#pragma unroll
    for (int i = 0; i < 8; i++) {
        v[i] = p[i * 32 + l];
        mx = fmaxf(mx, fmaxf(fmaxf(v[i].x, v[i].y), fmaxf(v[i].z, v[i].w)));
    }
#pragma unroll
    for (int o = 16; o > 0; o >>= 1) mx = fmaxf(mx, __shfl_xor_sync(0xffffffffu, mx, o));

    float sum = 0.f;
#pragma unroll
    for (int i = 0; i < 8; i++) {
        v[i].x = __expf(v[i].x - mx); v[i].y = __expf(v[i].y - mx);
        v[i].z = __expf(v[i].z - mx); v[i].w = __expf(v[i].w - mx);
        sum += (v[i].x + v[i].y) + (v[i].z + v[i].w);
    }
#pragma unroll
    for (int o = 16; o > 0; o >>= 1) sum += __shfl_xor_sync(0xffffffffu, sum, o);

    const float inv = 1.f / sum;
    __half* ph = g_ph + row * SEQ;
#pragma unroll
    for (int i = 0; i < 8; i++) {
        __half2 a = __floats2half2_rn(v[i].x * inv, v[i].y * inv);
        __half2 b = __floats2half2_rn(v[i].z * inv, v[i].w * inv);
        uint2 w;
        w.x = *reinterpret_cast<uint32_t*>(&a);
        w.y = *reinterpret_cast<uint32_t*>(&b);
        *(uint2*)(ph + (size_t)(i * 32 + l) * 4) = w;
    }
}

// ---------------------------------------------------------------------------
extern "C" void kernel_launch(void* const* d_in, const int* in_sizes, int n_in,
                              void* d_out, int out_size)
{
    const float* x  = (const float*)d_in[0];
    const float* Wq = (const float*)d_in[1];
    const float* bq = (const float*)d_in[2];
    const float* Wk = (const float*)d_in[3];
    const float* bk = (const float*)d_in[4];
    const float* Wv = (const float*)d_in[5];
    const float* bv = (const float*)d_in[6];
    float* out = (float*)d_out;

    cudaFuncSetAttribute(gemm3<M_PROJQK, 8>, cudaFuncAttributeMaxDynamicSharedMemorySize, SMEM_SZ);
    cudaFuncSetAttribute(gemm3<M_PROJVT, 8>, cudaFuncAttributeMaxDynamicSharedMemorySize, SMEM_SZ);
    cudaFuncSetAttribute(gemm3<M_QK, 8>,     cudaFuncAttributeMaxDynamicSharedMemorySize, SMEM_SZ);
    cudaFuncSetAttribute(gemm3<M_PV, 32>,    cudaFuncAttributeMaxDynamicSharedMemorySize, SMEM_SZ);

    split_x<<<(MTOT * EDIM) / 1024, 256>>>(x);
    transpose_split_w<<<3, 256>>>(Wq, Wk, Wv);

    gemm3<M_PROJQK, 8><<<dim3(MTOT / 128, 2),    512, SMEM_SZ>>>(bq, bk, bv, out);
    gemm3<M_PROJVT, 8><<<dim3(2, 4, BATCH),      512, SMEM_SZ>>>(bq, bk, bv, out);
    gemm3<M_QK, 8>    <<<dim3(8, 4, BATCH),      512, SMEM_SZ>>>(bq, bk, bv, out);
    softmax_rows      <<<MTOT / 8, 256>>>();
    gemm3<M_PV, 32>   <<<dim3(8, 1, BATCH),      512, SMEM_SZ>>>(bq, bk, bv, out);
}

// round 10
// speedup vs baseline: 1.1894x; 1.0683x over previous
#include <cuda_runtime.h>
#include <cuda_bf16.h>
#include <cuda_fp16.h>
#include <cstdint>

// ---------------------------------------------------------------------------
#define BATCH 64
#define SEQ   1024
#define EDIM  256
#define HDIM  256
#define MTOT  (BATCH * SEQ)       // 65536

// Pre-split operands, produced once, consumed by MMA mainloops.
__device__ __nv_bfloat16 g_xh [(size_t)MTOT * EDIM];
__device__ __nv_bfloat16 g_xl [(size_t)MTOT * EDIM];
__device__ __nv_bfloat16 g_qh [(size_t)MTOT * HDIM];
__device__ __nv_bfloat16 g_ql [(size_t)MTOT * HDIM];
__device__ __nv_bfloat16 g_kh [(size_t)MTOT * HDIM];
__device__ __nv_bfloat16 g_kl [(size_t)MTOT * HDIM];
__device__ __half        g_vth[(size_t)BATCH * EDIM * SEQ];   // V^T fp16 (single)
__device__ __half        g_ph [(size_t)BATCH * SEQ * SEQ];    // P fp16 (UNNORMALIZED)
__device__ float         g_l  [(size_t)MTOT];                 // per-row softmax sums
__device__ float         g_s  [(size_t)BATCH * SEQ * SEQ];    // fp32 logits
__device__ __nv_bfloat16 g_wqTh[EDIM * HDIM], g_wqTl[EDIM * HDIM];
__device__ __nv_bfloat16 g_wkTh[EDIM * HDIM], g_wkTl[EDIM * HDIM];
__device__ __nv_bfloat16 g_wvTh[EDIM * HDIM], g_wvTl[EDIM * HDIM];

// ---------------------------------------------------------------------------
// helpers
// ---------------------------------------------------------------------------
__device__ __forceinline__ uint32_t smem_u32(const void* p) {
    uint32_t a;
    asm("{ .reg .u64 t; cvta.to.shared.u64 t, %1; cvt.u32.u64 %0, t; }" : "=r"(a) : "l"(p));
    return a;
}
__device__ __forceinline__ void ldsm_x4(uint32_t* r, uint32_t addr) {
    asm volatile("ldmatrix.sync.aligned.m8n8.x4.shared.b16 {%0,%1,%2,%3}, [%4];"
                 : "=r"(r[0]), "=r"(r[1]), "=r"(r[2]), "=r"(r[3]) : "r"(addr));
}
__device__ __forceinline__ void mma_bf16(float* c, const uint32_t* a, const uint32_t* b) {
    asm volatile(
        "mma.sync.aligned.m16n8k16.row.col.f32.bf16.bf16.f32 "
        "{%0,%1,%2,%3}, {%4,%5,%6,%7}, {%8,%9}, {%0,%1,%2,%3};"
        : "+f"(c[0]), "+f"(c[1]), "+f"(c[2]), "+f"(c[3])
        : "r"(a[0]), "r"(a[1]), "r"(a[2]), "r"(a[3]), "r"(b[0]), "r"(b[1]));
}
__device__ __forceinline__ void mma_f16(float* c, const uint32_t* a, const uint32_t* b) {
    asm volatile(
        "mma.sync.aligned.m16n8k16.row.col.f32.f16.f16.f32 "
        "{%0,%1,%2,%3}, {%4,%5,%6,%7}, {%8,%9}, {%0,%1,%2,%3};"
        : "+f"(c[0]), "+f"(c[1]), "+f"(c[2]), "+f"(c[3])
        : "r"(a[0]), "r"(a[1]), "r"(a[2]), "r"(a[3]), "r"(b[0]), "r"(b[1]));
}
// hi/lo bf16 split of two floats, packed as bf16x2 words
__device__ __forceinline__ void split2(float x, float y, uint32_t& h, uint32_t& l) {
    __nv_bfloat162 H = __floats2bfloat162_rn(x, y);
    float hx = __bfloat162float(__low2bfloat16(H));
    float hy = __bfloat162float(__high2bfloat16(H));
    __nv_bfloat162 L = __floats2bfloat162_rn(x - hx, y - hy);
    h = *reinterpret_cast<uint32_t*>(&H);
    l = *reinterpret_cast<uint32_t*>(&L);
}

#define CP16(sm, gp)  asm volatile("cp.async.cg.shared.global [%0], [%1], 16;" :: "r"(sm), "l"(gp))
#define CP_COMMIT()   asm volatile("cp.async.commit_group;" ::: "memory")
#define CP_WAIT1()    asm volatile("cp.async.wait_group 1;" ::: "memory")

// ---------------------------------------------------------------------------
// GEMM: C[128 x 256] = A[128 x K] @ B[256 x K]^T.
// 256 threads, 8 warps (2m x 4n), warp tile 64x64 (mf=4, nf=8):
// 16 MAC/smem-byte vs 10.7 at 32x64 -- lifts the smem-bandwidth ceiling.
// K in chunks of 32; 3-stage cp.async pipeline, ONE __syncthreads per chunk.
// M_PV: 1-term fp16 (A = P~ fp16, B = V^T fp16), epilogue scales by 1/l.
// M_PROJBOTH: runtime-decoded projQK / projVT tiles (one launch).
// ---------------------------------------------------------------------------
#define ROWB   80
#define S_AH   0
#define S_AL   10240                 // 128*80
#define S_BH   20480
#define S_BL   40960                 // + 256*80
#define STAGE_SZ 61440
#define SMEM_SZ  (3 * STAGE_SZ)      // 184320

enum { M_PROJBOTH = 0, M_QK = 2, M_PV = 3 };

template<int MODE, int NCHUNK>
__global__ __launch_bounds__(256, 1)
void gemm3(const float* __restrict__ bq, const float* __restrict__ bk,
           const float* __restrict__ bv, float* __restrict__ outp)
{
    extern __shared__ __align__(128) char smem[];
    const uint32_t sbase = smem_u32(smem);
    const int t    = threadIdx.x;
    const int lane = t & 31;
    const int wid  = t >> 5;          // 0..7
    const int wm   = wid >> 2;        // 0..1  (64-row slab)
    const int wn   = wid & 3;         // 0..3  (64-col slab)

    // ---- operand resolution ----
    const uint16_t *Ah, *Al = nullptr, *Bh, *Bl = nullptr;
    __nv_bfloat16 *Ch = nullptr, *Cl = nullptr;
    __half *Chh = nullptr;
    float* Cf = nullptr;
    const float* bias = nullptr;
    const float* Lp = nullptr;
    size_t lda, ldb, ldc;
    int bias_mode = 0;   // 1: col bias -> bf16 hi/lo; 2: row bias -> fp16

    if (MODE == M_PROJBOTH) {
        int bx = blockIdx.x;
        if (bx < 1024) {   // projQK: q (qk=0) / k (qk=1)
            int qk = bx & 1, mt = bx >> 1;
            Ah = (const uint16_t*)(g_xh + (size_t)mt * 128 * EDIM);
            Al = (const uint16_t*)(g_xl + (size_t)mt * 128 * EDIM);                 lda = EDIM;
            Bh = (const uint16_t*)(qk ? g_wkTh : g_wqTh);
            Bl = (const uint16_t*)(qk ? g_wkTl : g_wqTl);                           ldb = EDIM;
            size_t co = (size_t)mt * 128 * HDIM;
            Ch = (qk ? g_kh : g_qh) + co;  Cl = (qk ? g_kl : g_ql) + co;            ldc = HDIM;
            bias = qk ? bk : bq;  bias_mode = 1;
        } else {           // projVT
            int r = bx - 1024;
            int mt = r & 1, nt = (r >> 1) & 3, b = r >> 3;
            Ah = (const uint16_t*)(g_wvTh + (size_t)mt * 128 * EDIM);
            Al = (const uint16_t*)(g_wvTl + (size_t)mt * 128 * EDIM);               lda = EDIM;
            size_t bo = ((size_t)b * SEQ + nt * 256) * EDIM;
            Bh = (const uint16_t*)(g_xh + bo);  Bl = (const uint16_t*)(g_xl + bo);  ldb = EDIM;
            Chh = g_vth + (size_t)b * EDIM * SEQ + (size_t)mt * 128 * SEQ + nt * 256; ldc = SEQ;
            bias = bv + mt * 128;  bias_mode = 2;
        }
    } else if (MODE == M_QK) {
        int mt = blockIdx.x, nt = blockIdx.y, b = blockIdx.z;
        size_t ao = ((size_t)b * SEQ + mt * 128) * HDIM;
        size_t bo = ((size_t)b * SEQ + nt * 256) * HDIM;
        Ah = (const uint16_t*)(g_qh + ao); Al = (const uint16_t*)(g_ql + ao);       lda = HDIM;
        Bh = (const uint16_t*)(g_kh + bo); Bl = (const uint16_t*)(g_kl + bo);       ldb = HDIM;
        Cf = g_s + (size_t)b * SEQ * SEQ + (size_t)mt * 128 * SEQ + nt * 256;       ldc = SEQ;
    } else { // M_PV: 1-term fp16, unnormalized P
        int mt = blockIdx.x, b = blockIdx.y;
        Ah = (const uint16_t*)(g_ph + (size_t)b * SEQ * SEQ + (size_t)mt * 128 * SEQ); lda = SEQ;
        Bh = (const uint16_t*)(g_vth + (size_t)b * EDIM * SEQ);                     ldb = SEQ;
        Cf = outp + ((size_t)b * SEQ + mt * 128) * EDIM;                            ldc = EDIM;
        Lp = g_l + (size_t)b * SEQ + mt * 128;
    }

    float acc[4][8][4];
#pragma unroll
    for (int i = 0; i < 4; i++)
#pragma unroll
        for (int j = 0; j < 8; j++)
#pragma unroll
            for (int e = 0; e < 4; e++) acc[i][j][e] = 0.f;

    // cp.async mapping (256 threads): A 128 rows x 64B (2 txns/plane),
    // B 256 rows x 64B (4 txns/plane).
    const int r_ld = t >> 2;             // 0..63
    const int cb16 = (t & 3) << 4;       // smem byte within row
    const int cel  = (t & 3) << 3;       // gmem element offset

#define LOAD_STAGE(J, BUF)                                                     \
    {                                                                          \
        const uint32_t sp = sbase + (uint32_t)(BUF) * STAGE_SZ;                \
        _Pragma("unroll")                                                      \
        for (int i = 0; i < 2; i++) {                                          \
            int r = r_ld + 64 * i;                                             \
            uint32_t so = (uint32_t)(r * ROWB + cb16);                         \
            size_t ga = (size_t)r * lda + (size_t)(J) * 32 + cel;              \
            CP16(sp + S_AH + so, Ah + ga);                                     \
            if (MODE != M_PV) CP16(sp + S_AL + so, Al + ga);                   \
        }                                                                      \
        _Pragma("unroll")                                                      \
        for (int i = 0; i < 4; i++) {                                          \
            int r = r_ld + 64 * i;                                             \
            uint32_t so = (uint32_t)(r * ROWB + cb16);                         \
            size_t gb = (size_t)r * ldb + (size_t)(J) * 32 + cel;              \
            CP16(sp + S_BH + so, Bh + gb);                                     \
            if (MODE != M_PV) CP16(sp + S_BL + so, Bl + gb);                   \
        }                                                                      \
    }

    // ldmatrix offsets (within a plane region)
    const uint32_t aoff = (uint32_t)((wm * 64 + (lane & 15)) * ROWB + ((lane >> 4) << 4));
    const uint32_t boff = (uint32_t)((wn * 64 + ((lane >> 4) << 3) + (lane & 7)) * ROWB
                                     + (((lane >> 3) & 1) << 4));

    // prologue: 2 stages in flight
    LOAD_STAGE(0, 0); CP_COMMIT();
    LOAD_STAGE(1, 1); CP_COMMIT();

#pragma unroll 1
    for (int j = 0; j < NCHUNK; j++) {
        CP_WAIT1();
        __syncthreads();    // single barrier per chunk

        const uint32_t st = sbase + (uint32_t)(j % 3) * STAGE_SZ;
#pragma unroll
        for (int ks = 0; ks < 2; ks++) {
            const uint32_t ko = (uint32_t)(ks * 32);
            uint32_t ah[4][4], al[4][4], b4[4][4];
#pragma unroll
            for (int mf = 0; mf < 4; mf++)
                ldsm_x4(ah[mf], st + S_AH + aoff + (uint32_t)(mf * 16 * ROWB) + ko);
#pragma unroll
            for (int ng = 0; ng < 4; ng++)
                ldsm_x4(b4[ng], st + S_BH + boff + (uint32_t)(ng * 16 * ROWB) + ko);

            if (MODE == M_PV) {
#pragma unroll
                for (int mf = 0; mf < 4; mf++)
#pragma unroll
                    for (int nf = 0; nf < 8; nf++)
                        mma_f16(acc[mf][nf], ah[mf], &b4[nf >> 1][(nf & 1) * 2]);
            } else {
#pragma unroll
                for (int mf = 0; mf < 4; mf++)
#pragma unroll
                    for (int nf = 0; nf < 8; nf++)
                        mma_bf16(acc[mf][nf], ah[mf], &b4[nf >> 1][(nf & 1) * 2]);
#pragma unroll
                for (int mf = 0; mf < 4; mf++)
                    ldsm_x4(al[mf], st + S_AL + aoff + (uint32_t)(mf * 16 * ROWB) + ko);
#pragma unroll
                for (int mf = 0; mf < 4; mf++)
#pragma unroll
                    for (int nf = 0; nf < 8; nf++)
                        mma_bf16(acc[mf][nf], al[mf], &b4[nf >> 1][(nf & 1) * 2]);
                // reload B regs with lo halves
#pragma unroll
                for (int ng = 0; ng < 4; ng++)
                    ldsm_x4(b4[ng], st + S_BL + boff + (uint32_t)(ng * 16 * ROWB) + ko);
#pragma unroll
                for (int mf = 0; mf < 4; mf++)
#pragma unroll
                    for (int nf = 0; nf < 8; nf++)
                        mma_bf16(acc[mf][nf], ah[mf], &b4[nf >> 1][(nf & 1) * 2]);
            }

            if (ks == 0) {   // issue next-stage loads between the two k-steps
                if (j + 2 < NCHUNK) LOAD_STAGE(j + 2, (j + 2) % 3);
                CP_COMMIT();
            }
        }
    }

    // ---- epilogue ----
#pragma unroll
    for (int mf = 0; mf < 4; mf++) {
        const int r0 = wm * 64 + mf * 16 + (lane >> 2);
        const int r1 = r0 + 8;
        float inv0 = 1.f, inv1 = 1.f;
        if (MODE == M_PV) { inv0 = 1.f / Lp[r0]; inv1 = 1.f / Lp[r1]; }
#pragma unroll
        for (int nf = 0; nf < 8; nf++) {
            const int c = wn * 64 + nf * 8 + ((lane & 3) << 1);
            float* a = acc[mf][nf];
            if (MODE == M_PROJBOTH) {
                if (bias_mode == 1) {
                    float cb0 = bias[c], cb1 = bias[c + 1];
                    uint32_t h, l;
                    split2(a[0] + cb0, a[1] + cb1, h, l);
                    *(uint32_t*)(Ch + (size_t)r0 * ldc + c) = h;
                    *(uint32_t*)(Cl + (size_t)r0 * ldc + c) = l;
                    split2(a[2] + cb0, a[3] + cb1, h, l);
                    *(uint32_t*)(Ch + (size_t)r1 * ldc + c) = h;
                    *(uint32_t*)(Cl + (size_t)r1 * ldc + c) = l;
                } else {
                    float rb0 = bias[r0], rb1 = bias[r1];
                    __half2 h0 = __floats2half2_rn(a[0] + rb0, a[1] + rb0);
                    __half2 h1 = __floats2half2_rn(a[2] + rb1, a[3] + rb1);
                    *(uint32_t*)(Chh + (size_t)r0 * ldc + c) = *reinterpret_cast<uint32_t*>(&h0);
                    *(uint32_t*)(Chh + (size_t)r1 * ldc + c) = *reinterpret_cast<uint32_t*>(&h1);
                }
            } else if (MODE == M_QK) {
                *(float2*)(Cf + (size_t)r0 * ldc + c) = make_float2(a[0], a[1]);
                *(float2*)(Cf + (size_t)r1 * ldc + c) = make_float2(a[2], a[3]);
            } else { // M_PV
                *(float2*)(Cf + (size_t)r0 * ldc + c) = make_float2(a[0] * inv0, a[1] * inv0);
                *(float2*)(Cf + (size_t)r1 * ldc + c) = make_float2(a[2] * inv1, a[3] * inv1);
            }
        }
    }
#undef LOAD_STAGE
}

// ---------------------------------------------------------------------------
// Prep (one launch): blocks [0,16384) split x into bf16 hi/lo;
// blocks [16384, 16384+24) transpose+split W (3 matrices x 8 row-slabs).
// ---------------------------------------------------------------------------
__global__ __launch_bounds__(256) void prep(const float* __restrict__ x,
                                            const float* __restrict__ Wq,
                                            const float* __restrict__ Wk,
                                            const float* __restrict__ Wv)
{
    const int bx = blockIdx.x;
    const int t  = threadIdx.x;
    if (bx < 16384) {
        size_t i = ((size_t)bx * 256 + t) * 4;
        float4 v = *(const float4*)(x + i);
        uint32_t h01, l01, h23, l23;
        split2(v.x, v.y, h01, l01);
        split2(v.z, v.w, h23, l23);
        *(uint2*)(g_xh + i) = make_uint2(h01, h23);
        *(uint2*)(g_xl + i) = make_uint2(l01, l23);
        return;
    }
    const int r2 = bx - 16384;      // 0..23
    const int m  = r2 >> 3;         // matrix
    const int ti = r2 & 7;          // 32-row slab of src
    const float* src = (m == 0) ? Wq : (m == 1) ? Wk : Wv;
    __nv_bfloat16* dh = (m == 0) ? g_wqTh : (m == 1) ? g_wkTh : g_wvTh;
    __nv_bfloat16* dl = (m == 0) ? g_wqTl : (m == 1) ? g_wkTl : g_wvTl;
    __shared__ float sm[32 * 33];
    const int w = t >> 5, l = t & 31;
    for (int tj = 0; tj < 8; tj++) {
#pragma unroll
        for (int k = 0; k < 4; k++) {
            int r = w * 4 + k;
            sm[r * 33 + l] = src[(size_t)(ti * 32 + r) * 256 + tj * 32 + l];
        }
        __syncthreads();
#pragma unroll
        for (int k = 0; k < 4; k++) {
            int r = w * 4 + k;
            float v = sm[l * 33 + r];
            __nv_bfloat16 h = __float2bfloat16_rn(v);
            float hv = __bfloat162float(h);
            dh[(size_t)(tj * 32 + r) * 256 + ti * 32 + l] = h;
            dl[(size_t)(tj * 32 + r) * 256 + ti * 32 + l] = __float2bfloat16_rn(v - hv);
        }
        __syncthreads();
    }
}

// ---------------------------------------------------------------------------
// Softmax: one warp per row. Writes UNNORMALIZED P~ = exp2((s-m)*log2e) as
// fp16 via h2exp2 (f16x2 MUFU, 2 exps/op), and the row sum to g_l.
// ---------------------------------------------------------------------------
__global__ __launch_bounds__(256) void softmax_rows()
{
    const size_t row = (size_t)blockIdx.x * 8 + (threadIdx.x >> 5);
    const int l = threadIdx.x & 31;
    const float4* p = (const float4*)(g_s + row * SEQ);

    float4 v[8];
    float mx = -3.4e38f;
#pragma unroll
    for (int i = 0; i < 8; i++) {
        v[i] = p[i * 32 + l];
        mx = fmaxf(mx, fmaxf(fmaxf(v[i].x, v[i].y), fmaxf(v[i].z, v[i].w)));
    }
#pragma unroll
    for (int o = 16; o > 0; o >>= 1) mx = fmaxf(mx, __shfl_xor_sync(0xffffffffu, mx, o));

    const float L2E = 1.4426950408889634f;
    const float mb  = -mx * L2E;
    float sum = 0.f;
    __half* ph = g_ph + row * SEQ;
#pragma unroll
    for (int i = 0; i < 8; i++) {
        __half2 y0 = __floats2half2_rn(fmaf(v[i].x, L2E, mb), fmaf(v[i].y, L2E, mb));
        __half2 y1 = __floats2half2_rn(fmaf(v[i].z, L2E, mb), fmaf(v[i].w, L2E, mb));
        __half2 e0 = h2exp2(y0);
        __half2 e1 = h2exp2(y1);
        float2 f0 = __half22float2(e0);
        float2 f1 = __half22float2(e1);
        sum += (f0.x + f0.y) + (f1.x + f1.y);
        uint2 w;
        w.x = *reinterpret_cast<uint32_t*>(&e0);
        w.y = *reinterpret_cast<uint32_t*>(&e1);
        *(uint2*)(ph + (size_t)(i * 32 + l) * 4) = w;
    }
#pragma unroll
    for (int o = 16; o > 0; o >>= 1) sum += __shfl_xor_sync(0xffffffffu, sum, o);
    if (l == 0) g_l[row] = sum;
}

// ---------------------------------------------------------------------------
extern "C" void kernel_launch(void* const* d_in, const int* in_sizes, int n_in,
                              void* d_out, int out_size)
{
    const float* x  = (const float*)d_in[0];
    const float* Wq = (const float*)d_in[1];
    const float* bq = (const float*)d_in[2];
    const float* Wk = (const float*)d_in[3];
    const float* bk = (const float*)d_in[4];
    const float* Wv = (const float*)d_in[5];
    const float* bv = (const float*)d_in[6];
    float* out = (float*)d_out;

    cudaFuncSetAttribute(gemm3<M_PROJBOTH, 8>, cudaFuncAttributeMaxDynamicSharedMemorySize, SMEM_SZ);
    cudaFuncSetAttribute(gemm3<M_QK, 8>,       cudaFuncAttributeMaxDynamicSharedMemorySize, SMEM_SZ);
    cudaFuncSetAttribute(gemm3<M_PV, 32>,      cudaFuncAttributeMaxDynamicSharedMemorySize, SMEM_SZ);

    prep<<<16384 + 24, 256>>>(x, Wq, Wk, Wv);

    gemm3<M_PROJBOTH, 8><<<1536,            256, SMEM_SZ>>>(bq, bk, bv, out);
    gemm3<M_QK, 8>      <<<dim3(8, 4, 64),  256, SMEM_SZ>>>(bq, bk, bv, out);
    softmax_rows        <<<MTOT / 8, 256>>>();
    gemm3<M_PV, 32>     <<<dim3(8, 64),     256, SMEM_SZ>>>(bq, bk, bv, out);
}

// round 11
// speedup vs baseline: 1.2276x; 1.0321x over previous
#include <cuda_runtime.h>
#include <cuda_bf16.h>
#include <cuda_fp16.h>
#include <cstdint>

// ---------------------------------------------------------------------------
#define BATCH 64
#define SEQ   1024
#define EDIM  256
#define HDIM  256
#define MTOT  (BATCH * SEQ)       // 65536

// Pre-split fp16 operands, produced once, consumed by MMA mainloops.
__device__ __half g_xh [(size_t)MTOT * EDIM];
__device__ __half g_xl [(size_t)MTOT * EDIM];
__device__ __half g_qh [(size_t)MTOT * HDIM];
__device__ __half g_ql [(size_t)MTOT * HDIM];
__device__ __half g_kh [(size_t)MTOT * HDIM];
__device__ __half g_kl [(size_t)MTOT * HDIM];
__device__ __half g_vth[(size_t)BATCH * EDIM * SEQ];   // V^T fp16 (single)
__device__ __half g_ph [(size_t)BATCH * SEQ * SEQ];    // P fp16 (UNNORMALIZED)
__device__ float  g_l  [(size_t)MTOT];                 // per-row softmax sums
__device__ float  g_s  [(size_t)BATCH * SEQ * SEQ];    // fp32 logits
__device__ __half g_wqTh[EDIM * HDIM], g_wqTl[EDIM * HDIM];
__device__ __half g_wkTh[EDIM * HDIM], g_wkTl[EDIM * HDIM];
__device__ __half g_wvTh[EDIM * HDIM], g_wvTl[EDIM * HDIM];

// ---------------------------------------------------------------------------
// helpers
// ---------------------------------------------------------------------------
__device__ __forceinline__ uint32_t smem_u32(const void* p) {
    uint32_t a;
    asm("{ .reg .u64 t; cvta.to.shared.u64 t, %1; cvt.u32.u64 %0, t; }" : "=r"(a) : "l"(p));
    return a;
}
__device__ __forceinline__ void ldsm_x4(uint32_t* r, uint32_t addr) {
    asm volatile("ldmatrix.sync.aligned.m8n8.x4.shared.b16 {%0,%1,%2,%3}, [%4];"
                 : "=r"(r[0]), "=r"(r[1]), "=r"(r[2]), "=r"(r[3]) : "r"(addr));
}
__device__ __forceinline__ void mma_f16(float* c, const uint32_t* a, const uint32_t* b) {
    asm volatile(
        "mma.sync.aligned.m16n8k16.row.col.f32.f16.f16.f32 "
        "{%0,%1,%2,%3}, {%4,%5,%6,%7}, {%8,%9}, {%0,%1,%2,%3};"
        : "+f"(c[0]), "+f"(c[1]), "+f"(c[2]), "+f"(c[3])
        : "r"(a[0]), "r"(a[1]), "r"(a[2]), "r"(a[3]), "r"(b[0]), "r"(b[1]));
}
// hi/lo fp16 split of two floats, packed as half2 words
__device__ __forceinline__ void split2h(float x, float y, uint32_t& h, uint32_t& l) {
    __half2 H = __floats2half2_rn(x, y);
    float hx = __half2float(__low2half(H));
    float hy = __half2float(__high2half(H));
    __half2 L = __floats2half2_rn(x - hx, y - hy);
    h = *reinterpret_cast<uint32_t*>(&H);
    l = *reinterpret_cast<uint32_t*>(&L);
}

#define CP16(sm, gp)  asm volatile("cp.async.cg.shared.global [%0], [%1], 16;" :: "r"(sm), "l"(gp))
#define CP_COMMIT()   asm volatile("cp.async.commit_group;" ::: "memory")
#define CP_WAIT1()    asm volatile("cp.async.wait_group 1;" ::: "memory")

// ---------------------------------------------------------------------------
// GEMM: C[128 x 256] = A[128 x K] @ B[256 x K]^T, fp16 hi/lo splits.
// 256 threads, 8 warps (2m x 4n), warp tile 64x64.
// K in chunks of 32; 3-stage cp.async pipeline, ONE __syncthreads per chunk.
// M_PROJBOTH decodes projQK (3-term) and projVT (2-term: A single fp16).
// M_QK: 3-term.
// ---------------------------------------------------------------------------
#define ROWB   80
#define S_AH   0
#define S_AL   10240                 // 128*80
#define S_BH   20480
#define S_BL   40960                 // + 256*80
#define STAGE_SZ 61440
#define SMEM_SZ  (3 * STAGE_SZ)      // 184320

enum { M_PROJBOTH = 0, M_QK = 2 };

template<int MODE, int NCHUNK>
__global__ __launch_bounds__(256, 1)
void gemm3(const float* __restrict__ bq, const float* __restrict__ bk,
           const float* __restrict__ bv)
{
    extern __shared__ __align__(128) char smem[];
    const uint32_t sbase = smem_u32(smem);
    const int t    = threadIdx.x;
    const int lane = t & 31;
    const int wid  = t >> 5;          // 0..7
    const int wm   = wid >> 2;        // 0..1  (64-row slab)
    const int wn   = wid & 3;         // 0..3  (64-col slab)

    // ---- operand resolution ----
    const uint16_t *Ah, *Al = nullptr, *Bh, *Bl;
    __half *Ch = nullptr, *Cl = nullptr, *Chh = nullptr;
    float* Cf = nullptr;
    const float* bias = nullptr;
    size_t lda, ldb, ldc;
    int bias_mode = 0;   // 1: col bias -> fp16 hi/lo out; 2: row bias -> fp16 single out

    if (MODE == M_PROJBOTH) {
        int bx = blockIdx.x;
        if (bx < 1024) {   // projQK: q (qk=0) / k (qk=1), 3-term
            int qk = bx & 1, mt = bx >> 1;
            Ah = (const uint16_t*)(g_xh + (size_t)mt * 128 * EDIM);
            Al = (const uint16_t*)(g_xl + (size_t)mt * 128 * EDIM);                 lda = EDIM;
            Bh = (const uint16_t*)(qk ? g_wkTh : g_wqTh);
            Bl = (const uint16_t*)(qk ? g_wkTl : g_wqTl);                           ldb = EDIM;
            size_t co = (size_t)mt * 128 * HDIM;
            Ch = (qk ? g_kh : g_qh) + co;  Cl = (qk ? g_kl : g_ql) + co;            ldc = HDIM;
            bias = qk ? bk : bq;  bias_mode = 1;
        } else {           // projVT: 2-term (A = Wv^T fp16 single)
            int r = bx - 1024;
            int mt = r & 1, nt = (r >> 1) & 3, b = r >> 3;
            Ah = (const uint16_t*)(g_wvTh + (size_t)mt * 128 * EDIM);               lda = EDIM;
            size_t bo = ((size_t)b * SEQ + nt * 256) * EDIM;
            Bh = (const uint16_t*)(g_xh + bo);  Bl = (const uint16_t*)(g_xl + bo);  ldb = EDIM;
            Chh = g_vth + (size_t)b * EDIM * SEQ + (size_t)mt * 128 * SEQ + nt * 256; ldc = SEQ;
            bias = bv + mt * 128;  bias_mode = 2;
        }
    } else { // M_QK: 3-term
        int mt = blockIdx.x, nt = blockIdx.y, b = blockIdx.z;
        size_t ao = ((size_t)b * SEQ + mt * 128) * HDIM;
        size_t bo = ((size_t)b * SEQ + nt * 256) * HDIM;
        Ah = (const uint16_t*)(g_qh + ao); Al = (const uint16_t*)(g_ql + ao);       lda = HDIM;
        Bh = (const uint16_t*)(g_kh + bo); Bl = (const uint16_t*)(g_kl + bo);       ldb = HDIM;
        Cf = g_s + (size_t)b * SEQ * SEQ + (size_t)mt * 128 * SEQ + nt * 256;       ldc = SEQ;
    }

    const bool use_alo = (MODE == M_QK) || (bias_mode == 1);

    float acc[4][8][4];
#pragma unroll
    for (int i = 0; i < 4; i++)
#pragma unroll
        for (int j = 0; j < 8; j++)
#pragma unroll
            for (int e = 0; e < 4; e++) acc[i][j][e] = 0.f;

    // cp.async mapping (256 threads): A 128 rows x 64B, B 256 rows x 64B.
    const int r_ld = t >> 2;             // 0..63
    const int cb16 = (t & 3) << 4;       // smem byte within row
    const int cel  = (t & 3) << 3;       // gmem element offset

#define LOAD_STAGE(J, BUF)                                                     \
    {                                                                          \
        const uint32_t sp = sbase + (uint32_t)(BUF) * STAGE_SZ;                \
        _Pragma("unroll")                                                      \
        for (int i = 0; i < 2; i++) {                                          \
            int r = r_ld + 64 * i;                                             \
            uint32_t so = (uint32_t)(r * ROWB + cb16);                         \
            size_t ga = (size_t)r * lda + (size_t)(J) * 32 + cel;              \
            CP16(sp + S_AH + so, Ah + ga);                                     \
            if (use_alo) CP16(sp + S_AL + so, Al + ga);                        \
        }                                                                      \
        _Pragma("unroll")                                                      \
        for (int i = 0; i < 4; i++) {                                          \
            int r = r_ld + 64 * i;                                             \
            uint32_t so = (uint32_t)(r * ROWB + cb16);                         \
            size_t gb = (size_t)r * ldb + (size_t)(J) * 32 + cel;              \
            CP16(sp + S_BH + so, Bh + gb);                                     \
            CP16(sp + S_BL + so, Bl + gb);                                     \
        }                                                                      \
    }

    // ldmatrix offsets (within a plane region)
    const uint32_t aoff = (uint32_t)((wm * 64 + (lane & 15)) * ROWB + ((lane >> 4) << 4));
    const uint32_t boff = (uint32_t)((wn * 64 + ((lane >> 4) << 3) + (lane & 7)) * ROWB
                                     + (((lane >> 3) & 1) << 4));

    // prologue: 2 stages in flight
    LOAD_STAGE(0, 0); CP_COMMIT();
    LOAD_STAGE(1, 1); CP_COMMIT();

#pragma unroll 1
    for (int j = 0; j < NCHUNK; j++) {
        CP_WAIT1();
        __syncthreads();    // single barrier per chunk

        const uint32_t st = sbase + (uint32_t)(j % 3) * STAGE_SZ;
#pragma unroll
        for (int ks = 0; ks < 2; ks++) {
            const uint32_t ko = (uint32_t)(ks * 32);
            uint32_t ah[4][4], al[4][4], b4[4][4];
#pragma unroll
            for (int mf = 0; mf < 4; mf++)
                ldsm_x4(ah[mf], st + S_AH + aoff + (uint32_t)(mf * 16 * ROWB) + ko);
#pragma unroll
            for (int ng = 0; ng < 4; ng++)
                ldsm_x4(b4[ng], st + S_BH + boff + (uint32_t)(ng * 16 * ROWB) + ko);
#pragma unroll
            for (int mf = 0; mf < 4; mf++)
#pragma unroll
                for (int nf = 0; nf < 8; nf++)
                    mma_f16(acc[mf][nf], ah[mf], &b4[nf >> 1][(nf & 1) * 2]);

            if (use_alo) {
#pragma unroll
                for (int mf = 0; mf < 4; mf++)
                    ldsm_x4(al[mf], st + S_AL + aoff + (uint32_t)(mf * 16 * ROWB) + ko);
#pragma unroll
                for (int mf = 0; mf < 4; mf++)
#pragma unroll
                    for (int nf = 0; nf < 8; nf++)
                        mma_f16(acc[mf][nf], al[mf], &b4[nf >> 1][(nf & 1) * 2]);
            }
            // reload B regs with lo halves
#pragma unroll
            for (int ng = 0; ng < 4; ng++)
                ldsm_x4(b4[ng], st + S_BL + boff + (uint32_t)(ng * 16 * ROWB) + ko);
#pragma unroll
            for (int mf = 0; mf < 4; mf++)
#pragma unroll
                for (int nf = 0; nf < 8; nf++)
                    mma_f16(acc[mf][nf], ah[mf], &b4[nf >> 1][(nf & 1) * 2]);

            if (ks == 0) {   // issue next-stage loads between the two k-steps
                if (j + 2 < NCHUNK) LOAD_STAGE(j + 2, (j + 2) % 3);
                CP_COMMIT();
            }
        }
    }

    // ---- epilogue ----
#pragma unroll
    for (int mf = 0; mf < 4; mf++) {
        const int r0 = wm * 64 + mf * 16 + (lane >> 2);
        const int r1 = r0 + 8;
#pragma unroll
        for (int nf = 0; nf < 8; nf++) {
            const int c = wn * 64 + nf * 8 + ((lane & 3) << 1);
            float* a = acc[mf][nf];
            if (MODE == M_PROJBOTH) {
                if (bias_mode == 1) {
                    float cb0 = bias[c], cb1 = bias[c + 1];
                    uint32_t h, l;
                    split2h(a[0] + cb0, a[1] + cb1, h, l);
                    *(uint32_t*)(Ch + (size_t)r0 * ldc + c) = h;
                    *(uint32_t*)(Cl + (size_t)r0 * ldc + c) = l;
                    split2h(a[2] + cb0, a[3] + cb1, h, l);
                    *(uint32_t*)(Ch + (size_t)r1 * ldc + c) = h;
                    *(uint32_t*)(Cl + (size_t)r1 * ldc + c) = l;
                } else {
                    float rb0 = bias[r0], rb1 = bias[r1];
                    __half2 h0 = __floats2half2_rn(a[0] + rb0, a[1] + rb0);
                    __half2 h1 = __floats2half2_rn(a[2] + rb1, a[3] + rb1);
                    *(uint32_t*)(Chh + (size_t)r0 * ldc + c) = *reinterpret_cast<uint32_t*>(&h0);
                    *(uint32_t*)(Chh + (size_t)r1 * ldc + c) = *reinterpret_cast<uint32_t*>(&h1);
                }
            } else {
                *(float2*)(Cf + (size_t)r0 * ldc + c) = make_float2(a[0], a[1]);
                *(float2*)(Cf + (size_t)r1 * ldc + c) = make_float2(a[2], a[3]);
            }
        }
    }
#undef LOAD_STAGE
}

// ---------------------------------------------------------------------------
// PV: O[128 x 256] = P~[128 x 1024] @ V^T[256 x 1024]^T, 1-term fp16.
// K-chunk 64 (half the barriers), 3-stage pipeline, rows 128B padded to 144B.
// Epilogue scales by 1/l.
// ---------------------------------------------------------------------------
#define PVROWB  144
#define PV_SA   0
#define PV_SB   18432                // 128*144
#define PV_STG  55296                // + 256*144
#define PV_SMEM (3 * PV_STG)         // 165888

__global__ __launch_bounds__(256, 1)
void gemm_pv(float* __restrict__ outp)
{
    extern __shared__ __align__(128) char smem[];
    const uint32_t sbase = smem_u32(smem);
    const int t    = threadIdx.x;
    const int lane = t & 31;
    const int wid  = t >> 5;
    const int wm   = wid >> 2;
    const int wn   = wid & 3;
    const int mt   = blockIdx.x;
    const int b    = blockIdx.y;

    const uint16_t* Ah = (const uint16_t*)(g_ph + (size_t)b * SEQ * SEQ + (size_t)mt * 128 * SEQ);
    const uint16_t* Bh = (const uint16_t*)(g_vth + (size_t)b * EDIM * SEQ);
    float* Cf = outp + ((size_t)b * SEQ + mt * 128) * EDIM;
    const float* Lp = g_l + (size_t)b * SEQ + mt * 128;

    float acc[4][8][4];
#pragma unroll
    for (int i = 0; i < 4; i++)
#pragma unroll
        for (int j = 0; j < 8; j++)
#pragma unroll
            for (int e = 0; e < 4; e++) acc[i][j][e] = 0.f;

#define PV_LOAD(J, BUF)                                                        \
    {                                                                          \
        const uint32_t sp = sbase + (uint32_t)(BUF) * PV_STG;                  \
        _Pragma("unroll")                                                      \
        for (int i = 0; i < 4; i++) {                                          \
            int idx = t + 256 * i;                                             \
            int r = idx >> 3, c16 = (idx & 7) << 4, ce = (idx & 7) << 3;       \
            CP16(sp + PV_SA + (uint32_t)(r * PVROWB + c16),                    \
                 Ah + (size_t)r * SEQ + (size_t)(J) * 64 + ce);                \
        }                                                                      \
        _Pragma("unroll")                                                      \
        for (int i = 0; i < 8; i++) {                                          \
            int idx = t + 256 * i;                                             \
            int r = idx >> 3, c16 = (idx & 7) << 4, ce = (idx & 7) << 3;       \
            CP16(sp + PV_SB + (uint32_t)(r * PVROWB + c16),                    \
                 Bh + (size_t)r * SEQ + (size_t)(J) * 64 + ce);                \
        }                                                                      \
    }

    const uint32_t aoff = (uint32_t)((wm * 64 + (lane & 15)) * PVROWB + ((lane >> 4) << 4));
    const uint32_t boff = (uint32_t)((wn * 64 + ((lane >> 4) << 3) + (lane & 7)) * PVROWB
                                     + (((lane >> 3) & 1) << 4));

    PV_LOAD(0, 0); CP_COMMIT();
    PV_LOAD(1, 1); CP_COMMIT();

#pragma unroll 1
    for (int j = 0; j < 16; j++) {
        CP_WAIT1();
        __syncthreads();

        const uint32_t st = sbase + (uint32_t)(j % 3) * PV_STG;
#pragma unroll
        for (int ks = 0; ks < 4; ks++) {
            const uint32_t ko = (uint32_t)(ks * 32);
            uint32_t ah[4][4], b4[4][4];
#pragma unroll
            for (int mf = 0; mf < 4; mf++)
                ldsm_x4(ah[mf], st + PV_SA + aoff + (uint32_t)(mf * 16 * PVROWB) + ko);
#pragma unroll
            for (int ng = 0; ng < 4; ng++)
                ldsm_x4(b4[ng], st + PV_SB + boff + (uint32_t)(ng * 16 * PVROWB) + ko);
#pragma unroll
            for (int mf = 0; mf < 4; mf++)
#pragma unroll
                for (int nf = 0; nf < 8; nf++)
                    mma_f16(acc[mf][nf], ah[mf], &b4[nf >> 1][(nf & 1) * 2]);

            if (ks == 0) {
                if (j + 2 < 16) PV_LOAD(j + 2, (j + 2) % 3);
                CP_COMMIT();
            }
        }
    }

#pragma unroll
    for (int mf = 0; mf < 4; mf++) {
        const int r0 = wm * 64 + mf * 16 + (lane >> 2);
        const int r1 = r0 + 8;
        const float inv0 = 1.f / Lp[r0];
        const float inv1 = 1.f / Lp[r1];
#pragma unroll
        for (int nf = 0; nf < 8; nf++) {
            const int c = wn * 64 + nf * 8 + ((lane & 3) << 1);
            float* a = acc[mf][nf];
            *(float2*)(Cf + (size_t)r0 * EDIM + c) = make_float2(a[0] * inv0, a[1] * inv0);
            *(float2*)(Cf + (size_t)r1 * EDIM + c) = make_float2(a[2] * inv1, a[3] * inv1);
        }
    }
#undef PV_LOAD
}

// ---------------------------------------------------------------------------
// Prep (one launch): blocks [0,16384) split x into fp16 hi/lo;
// blocks [16384, 16384+24) transpose+split W (3 matrices x 8 row-slabs).
// ---------------------------------------------------------------------------
__global__ __launch_bounds__(256) void prep(const float* __restrict__ x,
                                            const float* __restrict__ Wq,
                                            const float* __restrict__ Wk,
                                            const float* __restrict__ Wv)
{
    const int bx = blockIdx.x;
    const int t  = threadIdx.x;
    if (bx < 16384) {
        size_t i = ((size_t)bx * 256 + t) * 4;
        float4 v = *(const float4*)(x + i);
        uint32_t h01, l01, h23, l23;
        split2h(v.x, v.y, h01, l01);
        split2h(v.z, v.w, h23, l23);
        *(uint2*)(g_xh + i) = make_uint2(h01, h23);
        *(uint2*)(g_xl + i) = make_uint2(l01, l23);
        return;
    }
    const int r2 = bx - 16384;      // 0..23
    const int m  = r2 >> 3;         // matrix
    const int ti = r2 & 7;          // 32-row slab of src
    const float* src = (m == 0) ? Wq : (m == 1) ? Wk : Wv;
    __half* dh = (m == 0) ? g_wqTh : (m == 1) ? g_wkTh : g_wvTh;
    __half* dl = (m == 0) ? g_wqTl : (m == 1) ? g_wkTl : g_wvTl;
    __shared__ float sm[32 * 33];
    const int w = t >> 5, l = t & 31;
    for (int tj = 0; tj < 8; tj++) {
#pragma unroll
        for (int k = 0; k < 4; k++) {
            int r = w * 4 + k;
            sm[r * 33 + l] = src[(size_t)(ti * 32 + r) * 256 + tj * 32 + l];
        }
        __syncthreads();
#pragma unroll
        for (int k = 0; k < 4; k++) {
            int r = w * 4 + k;
            float v = sm[l * 33 + r];
            __half h = __float2half_rn(v);
            dh[(size_t)(tj * 32 + r) * 256 + ti * 32 + l] = h;
            dl[(size_t)(tj * 32 + r) * 256 + ti * 32 + l] = __float2half_rn(v - __half2float(h));
        }
        __syncthreads();
    }
}

// ---------------------------------------------------------------------------
// Softmax: one warp per row. Writes UNNORMALIZED P~ = exp2((s-m)*log2e) as
// fp16 via h2exp2, and the row sum to g_l.
// ---------------------------------------------------------------------------
__global__ __launch_bounds__(256) void softmax_rows()
{
    const size_t row = (size_t)blockIdx.x * 8 + (threadIdx.x >> 5);
    const int l = threadIdx.x & 31;
    const float4* p = (const float4*)(g_s + row * SEQ);

    float4 v[8];
    float mx = -3.4e38f;
#pragma unroll
    for (int i = 0; i < 8; i++) {
        v[i] = p[i * 32 + l];
        mx = fmaxf(mx, fmaxf(fmaxf(v[i].x, v[i].y), fmaxf(v[i].z, v[i].w)));
    }
#pragma unroll
    for (int o = 16; o > 0; o >>= 1) mx = fmaxf(mx, __shfl_xor_sync(0xffffffffu, mx, o));

    const float L2E = 1.4426950408889634f;
    const float mb  = -mx * L2E;
    float sum = 0.f;
    __half* ph = g_ph + row * SEQ;
#pragma unroll
    for (int i = 0; i < 8; i++) {
        __half2 y0 = __floats2half2_rn(fmaf(v[i].x, L2E, mb), fmaf(v[i].y, L2E, mb));
        __half2 y1 = __floats2half2_rn(fmaf(v[i].z, L2E, mb), fmaf(v[i].w, L2E, mb));
        __half2 e0 = h2exp2(y0);
        __half2 e1 = h2exp2(y1);
        float2 f0 = __half22float2(e0);
        float2 f1 = __half22float2(e1);
        sum += (f0.x + f0.y) + (f1.x + f1.y);
        uint2 w;
        w.x = *reinterpret_cast<uint32_t*>(&e0);
        w.y = *reinterpret_cast<uint32_t*>(&e1);
        *(uint2*)(ph + (size_t)(i * 32 + l) * 4) = w;
    }
#pragma unroll
    for (int o = 16; o > 0; o >>= 1) sum += __shfl_xor_sync(0xffffffffu, sum, o);
    if (l == 0) g_l[row] = sum;
}

// ---------------------------------------------------------------------------
extern "C" void kernel_launch(void* const* d_in, const int* in_sizes, int n_in,
                              void* d_out, int out_size)
{
    const float* x  = (const float*)d_in[0];
    const float* Wq = (const float*)d_in[1];
    const float* bq = (const float*)d_in[2];
    const float* Wk = (const float*)d_in[3];
    const float* bk = (const float*)d_in[4];
    const float* Wv = (const float*)d_in[5];
    const float* bv = (const float*)d_in[6];
    float* out = (float*)d_out;

    cudaFuncSetAttribute(gemm3<M_PROJBOTH, 8>, cudaFuncAttributeMaxDynamicSharedMemorySize, SMEM_SZ);
    cudaFuncSetAttribute(gemm3<M_QK, 8>,       cudaFuncAttributeMaxDynamicSharedMemorySize, SMEM_SZ);
    cudaFuncSetAttribute(gemm_pv,              cudaFuncAttributeMaxDynamicSharedMemorySize, PV_SMEM);

    prep<<<16384 + 24, 256>>>(x, Wq, Wk, Wv);

    gemm3<M_PROJBOTH, 8><<<1536,            256, SMEM_SZ>>>(bq, bk, bv);
    gemm3<M_QK, 8>      <<<dim3(8, 4, 64),  256, SMEM_SZ>>>(bq, bk, bv);
    softmax_rows        <<<MTOT / 8, 256>>>();
    gemm_pv             <<<dim3(8, 64),     256, PV_SMEM>>>(out);
}

// round 12
// speedup vs baseline: 1.2574x; 1.0242x over previous
#include <cuda_runtime.h>
#include <cuda_bf16.h>
#include <cuda_fp16.h>
#include <cstdint>

// ---------------------------------------------------------------------------
#define BATCH 64
#define SEQ   1024
#define EDIM  256
#define HDIM  256
#define MTOT  (BATCH * SEQ)       // 65536

// Pre-split fp16 operands, produced once, consumed by MMA mainloops.
__device__ __half g_xh [(size_t)MTOT * EDIM];
__device__ __half g_xl [(size_t)MTOT * EDIM];
__device__ __half g_qh [(size_t)MTOT * HDIM];
__device__ __half g_ql [(size_t)MTOT * HDIM];
__device__ __half g_kh [(size_t)MTOT * HDIM];
__device__ __half g_kl [(size_t)MTOT * HDIM];
__device__ __half g_vth[(size_t)BATCH * EDIM * SEQ];   // V^T fp16 (single)
__device__ __half g_ph [(size_t)BATCH * SEQ * SEQ];    // P fp16 (UNNORMALIZED)
__device__ float  g_l  [(size_t)MTOT];                 // per-row softmax sums
__device__ float  g_s  [(size_t)BATCH * SEQ * SEQ];    // fp32 logits
__device__ __half g_wqTh[EDIM * HDIM], g_wqTl[EDIM * HDIM];
__device__ __half g_wkTh[EDIM * HDIM], g_wkTl[EDIM * HDIM];
__device__ __half g_wvTh[EDIM * HDIM], g_wvTl[EDIM * HDIM];

// ---------------------------------------------------------------------------
// Host-side stream/event for graph fork (host objects; created at load time —
// only device-memory allocation is banned in static initializers).
// ---------------------------------------------------------------------------
static cudaStream_t g_s1;
static cudaEvent_t  g_e1, g_e2;
static struct _StreamInit {
    _StreamInit() {
        cudaStreamCreateWithFlags(&g_s1, cudaStreamNonBlocking);
        cudaEventCreateWithFlags(&g_e1, cudaEventDisableTiming);
        cudaEventCreateWithFlags(&g_e2, cudaEventDisableTiming);
    }
} g_stream_init;

// ---------------------------------------------------------------------------
// helpers
// ---------------------------------------------------------------------------
__device__ __forceinline__ uint32_t smem_u32(const void* p) {
    uint32_t a;
    asm("{ .reg .u64 t; cvta.to.shared.u64 t, %1; cvt.u32.u64 %0, t; }" : "=r"(a) : "l"(p));
    return a;
}
__device__ __forceinline__ void ldsm_x4(uint32_t* r, uint32_t addr) {
    asm volatile("ldmatrix.sync.aligned.m8n8.x4.shared.b16 {%0,%1,%2,%3}, [%4];"
                 : "=r"(r[0]), "=r"(r[1]), "=r"(r[2]), "=r"(r[3]) : "r"(addr));
}
__device__ __forceinline__ void mma_f16(float* c, const uint32_t* a, const uint32_t* b) {
    asm volatile(
        "mma.sync.aligned.m16n8k16.row.col.f32.f16.f16.f32 "
        "{%0,%1,%2,%3}, {%4,%5,%6,%7}, {%8,%9}, {%0,%1,%2,%3};"
        : "+f"(c[0]), "+f"(c[1]), "+f"(c[2]), "+f"(c[3])
        : "r"(a[0]), "r"(a[1]), "r"(a[2]), "r"(a[3]), "r"(b[0]), "r"(b[1]));
}
// hi/lo fp16 split of two floats, packed as half2 words
__device__ __forceinline__ void split2h(float x, float y, uint32_t& h, uint32_t& l) {
    __half2 H = __floats2half2_rn(x, y);
    float hx = __half2float(__low2half(H));
    float hy = __half2float(__high2half(H));
    __half2 L = __floats2half2_rn(x - hx, y - hy);
    h = *reinterpret_cast<uint32_t*>(&H);
    l = *reinterpret_cast<uint32_t*>(&L);
}

#define CP16(sm, gp)  asm volatile("cp.async.cg.shared.global [%0], [%1], 16;" :: "r"(sm), "l"(gp))
#define CP_COMMIT()   asm volatile("cp.async.commit_group;" ::: "memory")
#define CP_WAIT1()    asm volatile("cp.async.wait_group 1;" ::: "memory")

// ---------------------------------------------------------------------------
// GEMM: C[128 x 256] = A[128 x K] @ B[256 x K]^T, fp16 hi/lo splits.
// 256 threads, 8 warps (2m x 4n), warp tile 64x64.
// K in chunks of 32; 3-stage cp.async pipeline, ONE __syncthreads per chunk.
// M_PROJQK: 3-term. M_PROJVT: 2-term (A single fp16). M_QK: 3-term.
// ---------------------------------------------------------------------------
#define ROWB   80
#define S_AH   0
#define S_AL   10240                 // 128*80
#define S_BH   20480
#define S_BL   40960                 // + 256*80
#define STAGE_SZ 61440
#define SMEM_SZ  (3 * STAGE_SZ)      // 184320

enum { M_PROJQK = 0, M_PROJVT = 1, M_QK = 2 };

template<int MODE, int NCHUNK>
__global__ __launch_bounds__(256, 1)
void gemm3(const float* __restrict__ bq, const float* __restrict__ bk,
           const float* __restrict__ bv)
{
    extern __shared__ __align__(128) char smem[];
    const uint32_t sbase = smem_u32(smem);
    const int t    = threadIdx.x;
    const int lane = t & 31;
    const int wid  = t >> 5;          // 0..7
    const int wm   = wid >> 2;        // 0..1  (64-row slab)
    const int wn   = wid & 3;         // 0..3  (64-col slab)

    // ---- operand resolution ----
    const uint16_t *Ah, *Al = nullptr, *Bh, *Bl;
    __half *Ch = nullptr, *Cl = nullptr, *Chh = nullptr;
    float* Cf = nullptr;
    const float* bias = nullptr;
    size_t lda, ldb, ldc;

    if (MODE == M_PROJQK) {           // 3-term
        int mt = blockIdx.x, qk = blockIdx.y;
        Ah = (const uint16_t*)(g_xh + (size_t)mt * 128 * EDIM);
        Al = (const uint16_t*)(g_xl + (size_t)mt * 128 * EDIM);                 lda = EDIM;
        Bh = (const uint16_t*)(qk ? g_wkTh : g_wqTh);
        Bl = (const uint16_t*)(qk ? g_wkTl : g_wqTl);                           ldb = EDIM;
        size_t co = (size_t)mt * 128 * HDIM;
        Ch = (qk ? g_kh : g_qh) + co;  Cl = (qk ? g_kl : g_ql) + co;            ldc = HDIM;
        bias = qk ? bk : bq;
    } else if (MODE == M_PROJVT) {    // 2-term (A = Wv^T fp16 single)
        int mt = blockIdx.x, nt = blockIdx.y, b = blockIdx.z;
        Ah = (const uint16_t*)(g_wvTh + (size_t)mt * 128 * EDIM);               lda = EDIM;
        size_t bo = ((size_t)b * SEQ + nt * 256) * EDIM;
        Bh = (const uint16_t*)(g_xh + bo);  Bl = (const uint16_t*)(g_xl + bo);  ldb = EDIM;
        Chh = g_vth + (size_t)b * EDIM * SEQ + (size_t)mt * 128 * SEQ + nt * 256; ldc = SEQ;
        bias = bv + mt * 128;
    } else {                          // M_QK: 3-term
        int mt = blockIdx.x, nt = blockIdx.y, b = blockIdx.z;
        size_t ao = ((size_t)b * SEQ + mt * 128) * HDIM;
        size_t bo = ((size_t)b * SEQ + nt * 256) * HDIM;
        Ah = (const uint16_t*)(g_qh + ao); Al = (const uint16_t*)(g_ql + ao);   lda = HDIM;
        Bh = (const uint16_t*)(g_kh + bo); Bl = (const uint16_t*)(g_kl + bo);   ldb = HDIM;
        Cf = g_s + (size_t)b * SEQ * SEQ + (size_t)mt * 128 * SEQ + nt * 256;   ldc = SEQ;
    }

    const bool use_alo = (MODE != M_PROJVT);

    float acc[4][8][4];
#pragma unroll
    for (int i = 0; i < 4; i++)
#pragma unroll
        for (int j = 0; j < 8; j++)
#pragma unroll
            for (int e = 0; e < 4; e++) acc[i][j][e] = 0.f;

    // cp.async mapping (256 threads): A 128 rows x 64B, B 256 rows x 64B.
    const int r_ld = t >> 2;             // 0..63
    const int cb16 = (t & 3) << 4;       // smem byte within row
    const int cel  = (t & 3) << 3;       // gmem element offset

#define LOAD_STAGE(J, BUF)                                                     \
    {                                                                          \
        const uint32_t sp = sbase + (uint32_t)(BUF) * STAGE_SZ;                \
        _Pragma("unroll")                                                      \
        for (int i = 0; i < 2; i++) {                                          \
            int r = r_ld + 64 * i;                                             \
            uint32_t so = (uint32_t)(r * ROWB + cb16);                         \
            size_t ga = (size_t)r * lda + (size_t)(J) * 32 + cel;              \
            CP16(sp + S_AH + so, Ah + ga);                                     \
            if (use_alo) CP16(sp + S_AL + so, Al + ga);                        \
        }                                                                      \
        _Pragma("unroll")                                                      \
        for (int i = 0; i < 4; i++) {                                          \
            int r = r_ld + 64 * i;                                             \
            uint32_t so = (uint32_t)(r * ROWB + cb16);                         \
            size_t gb = (size_t)r * ldb + (size_t)(J) * 32 + cel;              \
            CP16(sp + S_BH + so, Bh + gb);                                     \
            CP16(sp + S_BL + so, Bl + gb);                                     \
        }                                                                      \
    }

    // ldmatrix offsets (within a plane region)
    const uint32_t aoff = (uint32_t)((wm * 64 + (lane & 15)) * ROWB + ((lane >> 4) << 4));
    const uint32_t boff = (uint32_t)((wn * 64 + ((lane >> 4) << 3) + (lane & 7)) * ROWB
                                     + (((lane >> 3) & 1) << 4));

    // prologue: 2 stages in flight
    LOAD_STAGE(0, 0); CP_COMMIT();
    LOAD_STAGE(1, 1); CP_COMMIT();

#pragma unroll 1
    for (int j = 0; j < NCHUNK; j++) {
        CP_WAIT1();
        __syncthreads();    // single barrier per chunk

        const uint32_t st = sbase + (uint32_t)(j % 3) * STAGE_SZ;
#pragma unroll
        for (int ks = 0; ks < 2; ks++) {
            const uint32_t ko = (uint32_t)(ks * 32);
            uint32_t ah[4][4], al[4][4], b4[4][4];
#pragma unroll
            for (int mf = 0; mf < 4; mf++)
                ldsm_x4(ah[mf], st + S_AH + aoff + (uint32_t)(mf * 16 * ROWB) + ko);
#pragma unroll
            for (int ng = 0; ng < 4; ng++)
                ldsm_x4(b4[ng], st + S_BH + boff + (uint32_t)(ng * 16 * ROWB) + ko);
#pragma unroll
            for (int mf = 0; mf < 4; mf++)
#pragma unroll
                for (int nf = 0; nf < 8; nf++)
                    mma_f16(acc[mf][nf], ah[mf], &b4[nf >> 1][(nf & 1) * 2]);

            if (use_alo) {
#pragma unroll
                for (int mf = 0; mf < 4; mf++)
                    ldsm_x4(al[mf], st + S_AL + aoff + (uint32_t)(mf * 16 * ROWB) + ko);
#pragma unroll
                for (int mf = 0; mf < 4; mf++)
#pragma unroll
                    for (int nf = 0; nf < 8; nf++)
                        mma_f16(acc[mf][nf], al[mf], &b4[nf >> 1][(nf & 1) * 2]);
            }
            // reload B regs with lo halves
#pragma unroll
            for (int ng = 0; ng < 4; ng++)
                ldsm_x4(b4[ng], st + S_BL + boff + (uint32_t)(ng * 16 * ROWB) + ko);
#pragma unroll
            for (int mf = 0; mf < 4; mf++)
#pragma unroll
                for (int nf = 0; nf < 8; nf++)
                    mma_f16(acc[mf][nf], ah[mf], &b4[nf >> 1][(nf & 1) * 2]);

            if (ks == 0) {   // issue next-stage loads between the two k-steps
                if (j + 2 < NCHUNK) LOAD_STAGE(j + 2, (j + 2) % 3);
                CP_COMMIT();
            }
        }
    }

    // ---- epilogue ----
#pragma unroll
    for (int mf = 0; mf < 4; mf++) {
        const int r0 = wm * 64 + mf * 16 + (lane >> 2);
        const int r1 = r0 + 8;
#pragma unroll
        for (int nf = 0; nf < 8; nf++) {
            const int c = wn * 64 + nf * 8 + ((lane & 3) << 1);
            float* a = acc[mf][nf];
            if (MODE == M_PROJQK) {
                float cb0 = bias[c], cb1 = bias[c + 1];
                uint32_t h, l;
                split2h(a[0] + cb0, a[1] + cb1, h, l);
                *(uint32_t*)(Ch + (size_t)r0 * ldc + c) = h;
                *(uint32_t*)(Cl + (size_t)r0 * ldc + c) = l;
                split2h(a[2] + cb0, a[3] + cb1, h, l);
                *(uint32_t*)(Ch + (size_t)r1 * ldc + c) = h;
                *(uint32_t*)(Cl + (size_t)r1 * ldc + c) = l;
            } else if (MODE == M_PROJVT) {
                float rb0 = bias[r0], rb1 = bias[r1];
                __half2 h0 = __floats2half2_rn(a[0] + rb0, a[1] + rb0);
                __half2 h1 = __floats2half2_rn(a[2] + rb1, a[3] + rb1);
                *(uint32_t*)(Chh + (size_t)r0 * ldc + c) = *reinterpret_cast<uint32_t*>(&h0);
                *(uint32_t*)(Chh + (size_t)r1 * ldc + c) = *reinterpret_cast<uint32_t*>(&h1);
            } else {
                *(float2*)(Cf + (size_t)r0 * ldc + c) = make_float2(a[0], a[1]);
                *(float2*)(Cf + (size_t)r1 * ldc + c) = make_float2(a[2], a[3]);
            }
        }
    }
#undef LOAD_STAGE
}

// ---------------------------------------------------------------------------
// PV: O[128 x 256] = P~[128 x 1024] @ V^T[256 x 1024]^T, 1-term fp16.
// K-chunk 64, 3-stage pipeline, rows 128B padded to 144B. Scales by 1/l.
// ---------------------------------------------------------------------------
#define PVROWB  144
#define PV_SA   0
#define PV_SB   18432                // 128*144
#define PV_STG  55296                // + 256*144
#define PV_SMEM (3 * PV_STG)         // 165888

__global__ __launch_bounds__(256, 1)
void gemm_pv(float* __restrict__ outp)
{
    extern __shared__ __align__(128) char smem[];
    const uint32_t sbase = smem_u32(smem);
    const int t    = threadIdx.x;
    const int lane = t & 31;
    const int wid  = t >> 5;
    const int wm   = wid >> 2;
    const int wn   = wid & 3;
    const int mt   = blockIdx.x;
    const int b    = blockIdx.y;

    const uint16_t* Ah = (const uint16_t*)(g_ph + (size_t)b * SEQ * SEQ + (size_t)mt * 128 * SEQ);
    const uint16_t* Bh = (const uint16_t*)(g_vth + (size_t)b * EDIM * SEQ);
    float* Cf = outp + ((size_t)b * SEQ + mt * 128) * EDIM;
    const float* Lp = g_l + (size_t)b * SEQ + mt * 128;

    float acc[4][8][4];
#pragma unroll
    for (int i = 0; i < 4; i++)
#pragma unroll
        for (int j = 0; j < 8; j++)
#pragma unroll
            for (int e = 0; e < 4; e++) acc[i][j][e] = 0.f;

#define PV_LOAD(J, BUF)                                                        \
    {                                                                          \
        const uint32_t sp = sbase + (uint32_t)(BUF) * PV_STG;                  \
        _Pragma("unroll")                                                      \
        for (int i = 0; i < 4; i++) {                                          \
            int idx = t + 256 * i;                                             \
            int r = idx >> 3, c16 = (idx & 7) << 4, ce = (idx & 7) << 3;       \
            CP16(sp + PV_SA + (uint32_t)(r * PVROWB + c16),                    \
                 Ah + (size_t)r * SEQ + (size_t)(J) * 64 + ce);                \
        }                                                                      \
        _Pragma("unroll")                                                      \
        for (int i = 0; i < 8; i++) {                                          \
            int idx = t + 256 * i;                                             \
            int r = idx >> 3, c16 = (idx & 7) << 4, ce = (idx & 7) << 3;       \
            CP16(sp + PV_SB + (uint32_t)(r * PVROWB + c16),                    \
                 Bh + (size_t)r * SEQ + (size_t)(J) * 64 + ce);                \
        }                                                                      \
    }

    const uint32_t aoff = (uint32_t)((wm * 64 + (lane & 15)) * PVROWB + ((lane >> 4) << 4));
    const uint32_t boff = (uint32_t)((wn * 64 + ((lane >> 4) << 3) + (lane & 7)) * PVROWB
                                     + (((lane >> 3) & 1) << 4));

    PV_LOAD(0, 0); CP_COMMIT();
    PV_LOAD(1, 1); CP_COMMIT();

#pragma unroll 1
    for (int j = 0; j < 16; j++) {
        CP_WAIT1();
        __syncthreads();

        const uint32_t st = sbase + (uint32_t)(j % 3) * PV_STG;
#pragma unroll
        for (int ks = 0; ks < 4; ks++) {
            const uint32_t ko = (uint32_t)(ks * 32);
            uint32_t ah[4][4], b4[4][4];
#pragma unroll
            for (int mf = 0; mf < 4; mf++)
                ldsm_x4(ah[mf], st + PV_SA + aoff + (uint32_t)(mf * 16 * PVROWB) + ko);
#pragma unroll
            for (int ng = 0; ng < 4; ng++)
                ldsm_x4(b4[ng], st + PV_SB + boff + (uint32_t)(ng * 16 * PVROWB) + ko);
#pragma unroll
            for (int mf = 0; mf < 4; mf++)
#pragma unroll
                for (int nf = 0; nf < 8; nf++)
                    mma_f16(acc[mf][nf], ah[mf], &b4[nf >> 1][(nf & 1) * 2]);

            if (ks == 0) {
                if (j + 2 < 16) PV_LOAD(j + 2, (j + 2) % 3);
                CP_COMMIT();
            }
        }
    }

#pragma unroll
    for (int mf = 0; mf < 4; mf++) {
        const int r0 = wm * 64 + mf * 16 + (lane >> 2);
        const int r1 = r0 + 8;
        const float inv0 = 1.f / Lp[r0];
        const float inv1 = 1.f / Lp[r1];
#pragma unroll
        for (int nf = 0; nf < 8; nf++) {
            const int c = wn * 64 + nf * 8 + ((lane & 3) << 1);
            float* a = acc[mf][nf];
            *(float2*)(Cf + (size_t)r0 * EDIM + c) = make_float2(a[0] * inv0, a[1] * inv0);
            *(float2*)(Cf + (size_t)r1 * EDIM + c) = make_float2(a[2] * inv1, a[3] * inv1);
        }
    }
#undef PV_LOAD
}

// ---------------------------------------------------------------------------
// Prep (one launch): blocks [0,16384) split x into fp16 hi/lo;
// blocks [16384, 16384+24) transpose+split W (3 matrices x 8 row-slabs).
// ---------------------------------------------------------------------------
__global__ __launch_bounds__(256) void prep(const float* __restrict__ x,
                                            const float* __restrict__ Wq,
                                            const float* __restrict__ Wk,
                                            const float* __restrict__ Wv)
{
    const int bx = blockIdx.x;
    const int t  = threadIdx.x;
    if (bx < 16384) {
        size_t i = ((size_t)bx * 256 + t) * 4;
        float4 v = *(const float4*)(x + i);
        uint32_t h01, l01, h23, l23;
        split2h(v.x, v.y, h01, l01);
        split2h(v.z, v.w, h23, l23);
        *(uint2*)(g_xh + i) = make_uint2(h01, h23);
        *(uint2*)(g_xl + i) = make_uint2(l01, l23);
        return;
    }
    const int r2 = bx - 16384;      // 0..23
    const int m  = r2 >> 3;         // matrix
    const int ti = r2 & 7;          // 32-row slab of src
    const float* src = (m == 0) ? Wq : (m == 1) ? Wk : Wv;
    __half* dh = (m == 0) ? g_wqTh : (m == 1) ? g_wkTh : g_wvTh;
    __half* dl = (m == 0) ? g_wqTl : (m == 1) ? g_wkTl : g_wvTl;
    __shared__ float sm[32 * 33];
    const int w = t >> 5, l = t & 31;
    for (int tj = 0; tj < 8; tj++) {
#pragma unroll
        for (int k = 0; k < 4; k++) {
            int r = w * 4 + k;
            sm[r * 33 + l] = src[(size_t)(ti * 32 + r) * 256 + tj * 32 + l];
        }
        __syncthreads();
#pragma unroll
        for (int k = 0; k < 4; k++) {
            int r = w * 4 + k;
            float v = sm[l * 33 + r];
            __half h = __float2half_rn(v);
            dh[(size_t)(tj * 32 + r) * 256 + ti * 32 + l] = h;
            dl[(size_t)(tj * 32 + r) * 256 + ti * 32 + l] = __float2half_rn(v - __half2float(h));
        }
        __syncthreads();
    }
}

// ---------------------------------------------------------------------------
// Softmax: one warp per row. Writes UNNORMALIZED P~ = exp2((s-m)*log2e) as
// fp16 via h2exp2, and the row sum to g_l.
// ---------------------------------------------------------------------------
__global__ __launch_bounds__(256) void softmax_rows()
{
    const size_t row = (size_t)blockIdx.x * 8 + (threadIdx.x >> 5);
    const int l = threadIdx.x & 31;
    const float4* p = (const float4*)(g_s + row * SEQ);

    float4 v[8];
    float mx = -3.4e38f;
#pragma unroll
    for (int i = 0; i < 8; i++) {
        v[i] = p[i * 32 + l];
        mx = fmaxf(mx, fmaxf(fmaxf(v[i].x, v[i].y), fmaxf(v[i].z, v[i].w)));
    }
#pragma unroll
    for (int o = 16; o > 0; o >>= 1) mx = fmaxf(mx, __shfl_xor_sync(0xffffffffu, mx, o));

    const float L2E = 1.4426950408889634f;
    const float mb  = -mx * L2E;
    float sum = 0.f;
    __half* ph = g_ph + row * SEQ;
#pragma unroll
    for (int i = 0; i < 8; i++) {
        __half2 y0 = __floats2half2_rn(fmaf(v[i].x, L2E, mb), fmaf(v[i].y, L2E, mb));
        __half2 y1 = __floats2half2_rn(fmaf(v[i].z, L2E, mb), fmaf(v[i].w, L2E, mb));
        __half2 e0 = h2exp2(y0);
        __half2 e1 = h2exp2(y1);
        float2 f0 = __half22float2(e0);
        float2 f1 = __half22float2(e1);
        sum += (f0.x + f0.y) + (f1.x + f1.y);
        uint2 w;
        w.x = *reinterpret_cast<uint32_t*>(&e0);
        w.y = *reinterpret_cast<uint32_t*>(&e1);
        *(uint2*)(ph + (size_t)(i * 32 + l) * 4) = w;
    }
#pragma unroll
    for (int o = 16; o > 0; o >>= 1) sum += __shfl_xor_sync(0xffffffffu, sum, o);
    if (l == 0) g_l[row] = sum;
}

// ---------------------------------------------------------------------------
extern "C" void kernel_launch(void* const* d_in, const int* in_sizes, int n_in,
                              void* d_out, int out_size)
{
    const float* x  = (const float*)d_in[0];
    const float* Wq = (const float*)d_in[1];
    const float* bq = (const float*)d_in[2];
    const float* Wk = (const float*)d_in[3];
    const float* bk = (const float*)d_in[4];
    const float* Wv = (const float*)d_in[5];
    const float* bv = (const float*)d_in[6];
    float* out = (float*)d_out;

    cudaFuncSetAttribute(gemm3<M_PROJQK, 8>, cudaFuncAttributeMaxDynamicSharedMemorySize, SMEM_SZ);
    cudaFuncSetAttribute(gemm3<M_PROJVT, 8>, cudaFuncAttributeMaxDynamicSharedMemorySize, SMEM_SZ);
    cudaFuncSetAttribute(gemm3<M_QK, 8>,     cudaFuncAttributeMaxDynamicSharedMemorySize, SMEM_SZ);
    cudaFuncSetAttribute(gemm_pv,            cudaFuncAttributeMaxDynamicSharedMemorySize, PV_SMEM);

    // main chain (default stream): prep -> projQK -> QK -> softmax -> PV
    prep<<<16384 + 24, 256>>>(x, Wq, Wk, Wv);

    // fork: projVT on side stream, concurrent with projQK/QK/softmax
    cudaEventRecord(g_e1, 0);
    cudaStreamWaitEvent(g_s1, g_e1, 0);
    gemm3<M_PROJVT, 8><<<dim3(2, 4, 64), 256, SMEM_SZ, g_s1>>>(bq, bk, bv);
    cudaEventRecord(g_e2, g_s1);

    gemm3<M_PROJQK, 8><<<dim3(512, 2),   256, SMEM_SZ>>>(bq, bk, bv);
    gemm3<M_QK, 8>    <<<dim3(8, 4, 64), 256, SMEM_SZ>>>(bq, bk, bv);
    softmax_rows      <<<MTOT / 8, 256>>>();

    // join: PV needs both softmax (default stream) and projVT (side stream)
    cudaStreamWaitEvent(0, g_e2, 0);
    gemm_pv<<<dim3(8, 64), 256, PV_SMEM>>>(out);
}

// round 13
// speedup vs baseline: 1.4155x; 1.1258x over previous
#include <cuda_runtime.h>
#include <cuda_bf16.h>
#include <cuda_fp16.h>
#include <cstdint>

// ---------------------------------------------------------------------------
#define BATCH 64
#define SEQ   1024
#define EDIM  256
#define HDIM  256
#define MTOT  (BATCH * SEQ)       // 65536

// Pre-split fp16 operands, produced once, consumed by MMA mainloops.
__device__ __half g_xh [(size_t)MTOT * EDIM];
__device__ __half g_xl [(size_t)MTOT * EDIM];
__device__ __half g_qh [(size_t)MTOT * HDIM];
__device__ __half g_ql [(size_t)MTOT * HDIM];
__device__ __half g_kh [(size_t)MTOT * HDIM];
__device__ __half g_kl [(size_t)MTOT * HDIM];
__device__ __half g_vth[(size_t)BATCH * EDIM * SEQ];   // V^T fp16 (single)
__device__ __half g_ph [(size_t)BATCH * SEQ * SEQ];    // P fp16 (UNNORMALIZED)
__device__ float  g_l  [(size_t)MTOT];                 // per-row softmax sums
__device__ float  g_s  [(size_t)BATCH * SEQ * SEQ];    // fp32 logits
__device__ __half g_wqTh[EDIM * HDIM], g_wqTl[EDIM * HDIM];
__device__ __half g_wkTh[EDIM * HDIM], g_wkTl[EDIM * HDIM];
__device__ __half g_wvTh[EDIM * HDIM], g_wvTl[EDIM * HDIM];

// ---------------------------------------------------------------------------
// Host-side stream/event for graph fork (host objects only).
// ---------------------------------------------------------------------------
static cudaStream_t g_s1;
static cudaEvent_t  g_e1, g_e2;
static struct _StreamInit {
    _StreamInit() {
        cudaStreamCreateWithFlags(&g_s1, cudaStreamNonBlocking);
        cudaEventCreateWithFlags(&g_e1, cudaEventDisableTiming);
        cudaEventCreateWithFlags(&g_e2, cudaEventDisableTiming);
    }
} g_stream_init;

// ---------------------------------------------------------------------------
// helpers
// ---------------------------------------------------------------------------
__device__ __forceinline__ uint32_t smem_u32(const void* p) {
    uint32_t a;
    asm("{ .reg .u64 t; cvta.to.shared.u64 t, %1; cvt.u32.u64 %0, t; }" : "=r"(a) : "l"(p));
    return a;
}
__device__ __forceinline__ void ldsm_x4(uint32_t* r, uint32_t addr) {
    asm volatile("ldmatrix.sync.aligned.m8n8.x4.shared.b16 {%0,%1,%2,%3}, [%4];"
                 : "=r"(r[0]), "=r"(r[1]), "=r"(r[2]), "=r"(r[3]) : "r"(addr));
}
__device__ __forceinline__ void mma_f16(float* c, const uint32_t* a, const uint32_t* b) {
    asm volatile(
        "mma.sync.aligned.m16n8k16.row.col.f32.f16.f16.f32 "
        "{%0,%1,%2,%3}, {%4,%5,%6,%7}, {%8,%9}, {%0,%1,%2,%3};"
        : "+f"(c[0]), "+f"(c[1]), "+f"(c[2]), "+f"(c[3])
        : "r"(a[0]), "r"(a[1]), "r"(a[2]), "r"(a[3]), "r"(b[0]), "r"(b[1]));
}
// hi/lo fp16 split of two floats, packed as half2 words
__device__ __forceinline__ void split2h(float x, float y, uint32_t& h, uint32_t& l) {
    __half2 H = __floats2half2_rn(x, y);
    float hx = __half2float(__low2half(H));
    float hy = __half2float(__high2half(H));
    __half2 L = __floats2half2_rn(x - hx, y - hy);
    h = *reinterpret_cast<uint32_t*>(&H);
    l = *reinterpret_cast<uint32_t*>(&L);
}

#define CP16(sm, gp)  asm volatile("cp.async.cg.shared.global [%0], [%1], 16;" :: "r"(sm), "l"(gp))
#define CP_COMMIT()   asm volatile("cp.async.commit_group;" ::: "memory")
#define CP_WAIT1()    asm volatile("cp.async.wait_group 1;" ::: "memory")

// ---------------------------------------------------------------------------
// GEMM: C[128 x 256] = A[128 x K] @ B[256 x K]^T, fp16 hi/lo splits.
// 256 threads, 8 warps (2m x 4n), warp tile 64x64.
// K in chunks of 32; 3-stage cp.async pipeline, ONE __syncthreads per chunk.
// Term structure per mode:
//   M_PROJQK: 3-term  (A hi/lo, B hi/lo)   -- precision-critical
//   M_PROJVT: 2-term  (A hi only, B hi/lo)
//   M_QK:     2-term  (A hi/lo, B hi only) -- (ah+al)*bh = a_exact*bh
// ---------------------------------------------------------------------------
#define ROWB   80
#define S_AH   0
#define S_AL   10240                 // 128*80
#define S_BH   20480
#define S_BL   40960                 // + 256*80
#define STAGE_SZ 61440
#define SMEM_SZ  (3 * STAGE_SZ)      // 184320

enum { M_PROJQK = 0, M_PROJVT = 1, M_QK = 2 };

template<int MODE, int NCHUNK>
__global__ __launch_bounds__(256, 1)
void gemm3(const float* __restrict__ bq, const float* __restrict__ bk,
           const float* __restrict__ bv)
{
    extern __shared__ __align__(128) char smem[];
    const uint32_t sbase = smem_u32(smem);
    const int t    = threadIdx.x;
    const int lane = t & 31;
    const int wid  = t >> 5;          // 0..7
    const int wm   = wid >> 2;        // 0..1  (64-row slab)
    const int wn   = wid & 3;         // 0..3  (64-col slab)

    constexpr bool USE_ALO = (MODE != M_PROJVT);
    constexpr bool USE_BLO = (MODE != M_QK);

    // ---- operand resolution ----
    const uint16_t *Ah, *Al = nullptr, *Bh, *Bl = nullptr;
    __half *Ch = nullptr, *Cl = nullptr, *Chh = nullptr;
    float* Cf = nullptr;
    const float* bias = nullptr;
    size_t lda, ldb, ldc;

    if (MODE == M_PROJQK) {
        int mt = blockIdx.x, qk = blockIdx.y;
        Ah = (const uint16_t*)(g_xh + (size_t)mt * 128 * EDIM);
        Al = (const uint16_t*)(g_xl + (size_t)mt * 128 * EDIM);                 lda = EDIM;
        Bh = (const uint16_t*)(qk ? g_wkTh : g_wqTh);
        Bl = (const uint16_t*)(qk ? g_wkTl : g_wqTl);                           ldb = EDIM;
        size_t co = (size_t)mt * 128 * HDIM;
        Ch = (qk ? g_kh : g_qh) + co;  Cl = (qk ? g_kl : g_ql) + co;            ldc = HDIM;
        bias = qk ? bk : bq;
    } else if (MODE == M_PROJVT) {
        int mt = blockIdx.x, nt = blockIdx.y, b = blockIdx.z;
        Ah = (const uint16_t*)(g_wvTh + (size_t)mt * 128 * EDIM);               lda = EDIM;
        size_t bo = ((size_t)b * SEQ + nt * 256) * EDIM;
        Bh = (const uint16_t*)(g_xh + bo);  Bl = (const uint16_t*)(g_xl + bo);  ldb = EDIM;
        Chh = g_vth + (size_t)b * EDIM * SEQ + (size_t)mt * 128 * SEQ + nt * 256; ldc = SEQ;
        bias = bv + mt * 128;
    } else {                          // M_QK: 2-term, no B-lo
        int mt = blockIdx.x, nt = blockIdx.y, b = blockIdx.z;
        size_t ao = ((size_t)b * SEQ + mt * 128) * HDIM;
        size_t bo = ((size_t)b * SEQ + nt * 256) * HDIM;
        Ah = (const uint16_t*)(g_qh + ao); Al = (const uint16_t*)(g_ql + ao);   lda = HDIM;
        Bh = (const uint16_t*)(g_kh + bo);                                      ldb = HDIM;
        Cf = g_s + (size_t)b * SEQ * SEQ + (size_t)mt * 128 * SEQ + nt * 256;   ldc = SEQ;
    }

    float acc[4][8][4];
#pragma unroll
    for (int i = 0; i < 4; i++)
#pragma unroll
        for (int j = 0; j < 8; j++)
#pragma unroll
            for (int e = 0; e < 4; e++) acc[i][j][e] = 0.f;

    // cp.async mapping (256 threads): A 128 rows x 64B, B 256 rows x 64B.
    const int r_ld = t >> 2;             // 0..63
    const int cb16 = (t & 3) << 4;       // smem byte within row
    const int cel  = (t & 3) << 3;       // gmem element offset

#define LOAD_STAGE(J, BUF)                                                     \
    {                                                                          \
        const uint32_t sp = sbase + (uint32_t)(BUF) * STAGE_SZ;                \
        _Pragma("unroll")                                                      \
        for (int i = 0; i < 2; i++) {                                          \
            int r = r_ld + 64 * i;                                             \
            uint32_t so = (uint32_t)(r * ROWB + cb16);                         \
            size_t ga = (size_t)r * lda + (size_t)(J) * 32 + cel;              \
            CP16(sp + S_AH + so, Ah + ga);                                     \
            if (USE_ALO) CP16(sp + S_AL + so, Al + ga);                        \
        }                                                                      \
        _Pragma("unroll")                                                      \
        for (int i = 0; i < 4; i++) {                                          \
            int r = r_ld + 64 * i;                                             \
            uint32_t so = (uint32_t)(r * ROWB + cb16);                         \
            size_t gb = (size_t)r * ldb + (size_t)(J) * 32 + cel;              \
            CP16(sp + S_BH + so, Bh + gb);                                     \
            if (USE_BLO) CP16(sp + S_BL + so, Bl + gb);                        \
        }                                                                      \
    }

    // ldmatrix offsets (within a plane region)
    const uint32_t aoff = (uint32_t)((wm * 64 + (lane & 15)) * ROWB + ((lane >> 4) << 4));
    const uint32_t boff = (uint32_t)((wn * 64 + ((lane >> 4) << 3) + (lane & 7)) * ROWB
                                     + (((lane >> 3) & 1) << 4));

    // prologue: 2 stages in flight
    LOAD_STAGE(0, 0); CP_COMMIT();
    LOAD_STAGE(1, 1); CP_COMMIT();

#pragma unroll 1
    for (int j = 0; j < NCHUNK; j++) {
        CP_WAIT1();
        __syncthreads();    // single barrier per chunk

        const uint32_t st = sbase + (uint32_t)(j % 3) * STAGE_SZ;
#pragma unroll
        for (int ks = 0; ks < 2; ks++) {
            const uint32_t ko = (uint32_t)(ks * 32);
            uint32_t ah[4][4], al[4][4], b4[4][4];
#pragma unroll
            for (int mf = 0; mf < 4; mf++)
                ldsm_x4(ah[mf], st + S_AH + aoff + (uint32_t)(mf * 16 * ROWB) + ko);
#pragma unroll
            for (int ng = 0; ng < 4; ng++)
                ldsm_x4(b4[ng], st + S_BH + boff + (uint32_t)(ng * 16 * ROWB) + ko);
#pragma unroll
            for (int mf = 0; mf < 4; mf++)
#pragma unroll
                for (int nf = 0; nf < 8; nf++)
                    mma_f16(acc[mf][nf], ah[mf], &b4[nf >> 1][(nf & 1) * 2]);

            if (USE_ALO) {
#pragma unroll
                for (int mf = 0; mf < 4; mf++)
                    ldsm_x4(al[mf], st + S_AL + aoff + (uint32_t)(mf * 16 * ROWB) + ko);
#pragma unroll
                for (int mf = 0; mf < 4; mf++)
#pragma unroll
                    for (int nf = 0; nf < 8; nf++)
                        mma_f16(acc[mf][nf], al[mf], &b4[nf >> 1][(nf & 1) * 2]);
            }
            if (USE_BLO) {
                // reload B regs with lo halves
#pragma unroll
                for (int ng = 0; ng < 4; ng++)
                    ldsm_x4(b4[ng], st + S_BL + boff + (uint32_t)(ng * 16 * ROWB) + ko);
#pragma unroll
                for (int mf = 0; mf < 4; mf++)
#pragma unroll
                    for (int nf = 0; nf < 8; nf++)
                        mma_f16(acc[mf][nf], ah[mf], &b4[nf >> 1][(nf & 1) * 2]);
            }

            if (ks == 0) {   // issue next-stage loads between the two k-steps
                if (j + 2 < NCHUNK) LOAD_STAGE(j + 2, (j + 2) % 3);
                CP_COMMIT();
            }
        }
    }

    // ---- epilogue ----
#pragma unroll
    for (int mf = 0; mf < 4; mf++) {
        const int r0 = wm * 64 + mf * 16 + (lane >> 2);
        const int r1 = r0 + 8;
#pragma unroll
        for (int nf = 0; nf < 8; nf++) {
            const int c = wn * 64 + nf * 8 + ((lane & 3) << 1);
            float* a = acc[mf][nf];
            if (MODE == M_PROJQK) {
                float cb0 = bias[c], cb1 = bias[c + 1];
                uint32_t h, l;
                split2h(a[0] + cb0, a[1] + cb1, h, l);
                *(uint32_t*)(Ch + (size_t)r0 * ldc + c) = h;
                *(uint32_t*)(Cl + (size_t)r0 * ldc + c) = l;
                split2h(a[2] + cb0, a[3] + cb1, h, l);
                *(uint32_t*)(Ch + (size_t)r1 * ldc + c) = h;
                *(uint32_t*)(Cl + (size_t)r1 * ldc + c) = l;
            } else if (MODE == M_PROJVT) {
                float rb0 = bias[r0], rb1 = bias[r1];
                __half2 h0 = __floats2half2_rn(a[0] + rb0, a[1] + rb0);
                __half2 h1 = __floats2half2_rn(a[2] + rb1, a[3] + rb1);
                *(uint32_t*)(Chh + (size_t)r0 * ldc + c) = *reinterpret_cast<uint32_t*>(&h0);
                *(uint32_t*)(Chh + (size_t)r1 * ldc + c) = *reinterpret_cast<uint32_t*>(&h1);
            } else {
                *(float2*)(Cf + (size_t)r0 * ldc + c) = make_float2(a[0], a[1]);
                *(float2*)(Cf + (size_t)r1 * ldc + c) = make_float2(a[2], a[3]);
            }
        }
    }
#undef LOAD_STAGE
}

// ---------------------------------------------------------------------------
// PV: O[128 x 256] = P~[128 x 1024] @ V^T[256 x 1024]^T, 1-term fp16.
// K-chunk 64, 3-stage pipeline, rows 128B padded to 144B. Scales by 1/l.
// ---------------------------------------------------------------------------
#define PVROWB  144
#define PV_SA   0
#define PV_SB   18432                // 128*144
#define PV_STG  55296                // + 256*144
#define PV_SMEM (3 * PV_STG)         // 165888

__global__ __launch_bounds__(256, 1)
void gemm_pv(float* __restrict__ outp)
{
    extern __shared__ __align__(128) char smem[];
    const uint32_t sbase = smem_u32(smem);
    const int t    = threadIdx.x;
    const int lane = t & 31;
    const int wid  = t >> 5;
    const int wm   = wid >> 2;
    const int wn   = wid & 3;
    const int mt   = blockIdx.x;
    const int b    = blockIdx.y;

    const uint16_t* Ah = (const uint16_t*)(g_ph + (size_t)b * SEQ * SEQ + (size_t)mt * 128 * SEQ);
    const uint16_t* Bh = (const uint16_t*)(g_vth + (size_t)b * EDIM * SEQ);
    float* Cf = outp + ((size_t)b * SEQ + mt * 128) * EDIM;
    const float* Lp = g_l + (size_t)b * SEQ + mt * 128;

    float acc[4][8][4];
#pragma unroll
    for (int i = 0; i < 4; i++)
#pragma unroll
        for (int j = 0; j < 8; j++)
#pragma unroll
            for (int e = 0; e < 4; e++) acc[i][j][e] = 0.f;

#define PV_LOAD(J, BUF)                                                        \
    {                                                                          \
        const uint32_t sp = sbase + (uint32_t)(BUF) * PV_STG;                  \
        _Pragma("unroll")                                                      \
        for (int i = 0; i < 4; i++) {                                          \
            int idx = t + 256 * i;                                             \
            int r = idx >> 3, c16 = (idx & 7) << 4, ce = (idx & 7) << 3;       \
            CP16(sp + PV_SA + (uint32_t)(r * PVROWB + c16),                    \
                 Ah + (size_t)r * SEQ + (size_t)(J) * 64 + ce);                \
        }                                                                      \
        _Pragma("unroll")                                                      \
        for (int i = 0; i < 8; i++) {                                          \
            int idx = t + 256 * i;                                             \
            int r = idx >> 3, c16 = (idx & 7) << 4, ce = (idx & 7) << 3;       \
            CP16(sp + PV_SB + (uint32_t)(r * PVROWB + c16),                    \
                 Bh + (size_t)r * SEQ + (size_t)(J) * 64 + ce);                \
        }                                                                      \
    }

    const uint32_t aoff = (uint32_t)((wm * 64 + (lane & 15)) * PVROWB + ((lane >> 4) << 4));
    const uint32_t boff = (uint32_t)((wn * 64 + ((lane >> 4) << 3) + (lane & 7)) * PVROWB
                                     + (((lane >> 3) & 1) << 4));

    PV_LOAD(0, 0); CP_COMMIT();
    PV_LOAD(1, 1); CP_COMMIT();

#pragma unroll 1
    for (int j = 0; j < 16; j++) {
        CP_WAIT1();
        __syncthreads();

        const uint32_t st = sbase + (uint32_t)(j % 3) * PV_STG;
#pragma unroll
        for (int ks = 0; ks < 4; ks++) {
            const uint32_t ko = (uint32_t)(ks * 32);
            uint32_t ah[4][4], b4[4][4];
#pragma unroll
            for (int mf = 0; mf < 4; mf++)
                ldsm_x4(ah[mf], st + PV_SA + aoff + (uint32_t)(mf * 16 * PVROWB) + ko);
#pragma unroll
            for (int ng = 0; ng < 4; ng++)
                ldsm_x4(b4[ng], st + PV_SB + boff + (uint32_t)(ng * 16 * PVROWB) + ko);
#pragma unroll
            for (int mf = 0; mf < 4; mf++)
#pragma unroll
                for (int nf = 0; nf < 8; nf++)
                    mma_f16(acc[mf][nf], ah[mf], &b4[nf >> 1][(nf & 1) * 2]);

            if (ks == 0) {
                if (j + 2 < 16) PV_LOAD(j + 2, (j + 2) % 3);
                CP_COMMIT();
            }
        }
    }

#pragma unroll
    for (int mf = 0; mf < 4; mf++) {
        const int r0 = wm * 64 + mf * 16 + (lane >> 2);
        const int r1 = r0 + 8;
        const float inv0 = 1.f / Lp[r0];
        const float inv1 = 1.f / Lp[r1];
#pragma unroll
        for (int nf = 0; nf < 8; nf++) {
            const int c = wn * 64 + nf * 8 + ((lane & 3) << 1);
            float* a = acc[mf][nf];
            *(float2*)(Cf + (size_t)r0 * EDIM + c) = make_float2(a[0] * inv0, a[1] * inv0);
            *(float2*)(Cf + (size_t)r1 * EDIM + c) = make_float2(a[2] * inv1, a[3] * inv1);
        }
    }
#undef PV_LOAD
}

// ---------------------------------------------------------------------------
// Prep (one launch): blocks [0,16384) split x into fp16 hi/lo;
// blocks [16384, 16384+24) transpose+split W (3 matrices x 8 row-slabs).
// ---------------------------------------------------------------------------
__global__ __launch_bounds__(256) void prep(const float* __restrict__ x,
                                            const float* __restrict__ Wq,
                                            const float* __restrict__ Wk,
                                            const float* __restrict__ Wv)
{
    const int bx = blockIdx.x;
    const int t  = threadIdx.x;
    if (bx < 16384) {
        size_t i = ((size_t)bx * 256 + t) * 4;
        float4 v = *(const float4*)(x + i);
        uint32_t h01, l01, h23, l23;
        split2h(v.x, v.y, h01, l01);
        split2h(v.z, v.w, h23, l23);
        *(uint2*)(g_xh + i) = make_uint2(h01, h23);
        *(uint2*)(g_xl + i) = make_uint2(l01, l23);
        return;
    }
    const int r2 = bx - 16384;      // 0..23
    const int m  = r2 >> 3;         // matrix
    const int ti = r2 & 7;          // 32-row slab of src
    const float* src = (m == 0) ? Wq : (m == 1) ? Wk : Wv;
    __half* dh = (m == 0) ? g_wqTh : (m == 1) ? g_wkTh : g_wvTh;
    __half* dl = (m == 0) ? g_wqTl : (m == 1) ? g_wkTl : g_wvTl;
    __shared__ float sm[32 * 33];
    const int w = t >> 5, l = t & 31;
    for (int tj = 0; tj < 8; tj++) {
#pragma unroll
        for (int k = 0; k < 4; k++) {
            int r = w * 4 + k;
            sm[r * 33 + l] = src[(size_t)(ti * 32 + r) * 256 + tj * 32 + l];
        }
        __syncthreads();
#pragma unroll
        for (int k = 0; k < 4; k++) {
            int r = w * 4 + k;
            float v = sm[l * 33 + r];
            __half h = __float2half_rn(v);
            dh[(size_t)(tj * 32 + r) * 256 + ti * 32 + l] = h;
            dl[(size_t)(tj * 32 + r) * 256 + ti * 32 + l] = __float2half_rn(v - __half2float(h));
        }
        __syncthreads();
    }
}

// ---------------------------------------------------------------------------
// Softmax: one warp per row. Writes UNNORMALIZED P~ = exp2((s-m)*log2e) as
// fp16 via h2exp2, and the row sum to g_l.
// ---------------------------------------------------------------------------
__global__ __launch_bounds__(256) void softmax_rows()
{
    const size_t row = (size_t)blockIdx.x * 8 + (threadIdx.x >> 5);
    const int l = threadIdx.x & 31;
    const float4* p = (const float4*)(g_s + row * SEQ);

    float4 v[8];
    float mx = -3.4e38f;
#pragma unroll
    for (int i = 0; i < 8; i++) {
        v[i] = p[i * 32 + l];
        mx = fmaxf(mx, fmaxf(fmaxf(v[i].x, v[i].y), fmaxf(v[i].z, v[i].w)));
    }
#pragma unroll
    for (int o = 16; o > 0; o >>= 1) mx = fmaxf(mx, __shfl_xor_sync(0xffffffffu, mx, o));

    const float L2E = 1.4426950408889634f;
    const float mb  = -mx * L2E;
    float sum = 0.f;
    __half* ph = g_ph + row * SEQ;
#pragma unroll
    for (int i = 0; i < 8; i++) {
        __half2 y0 = __floats2half2_rn(fmaf(v[i].x, L2E, mb), fmaf(v[i].y, L2E, mb));
        __half2 y1 = __floats2half2_rn(fmaf(v[i].z, L2E, mb), fmaf(v[i].w, L2E, mb));
        __half2 e0 = h2exp2(y0);
        __half2 e1 = h2exp2(y1);
        float2 f0 = __half22float2(e0);
        float2 f1 = __half22float2(e1);
        sum += (f0.x + f0.y) + (f1.x + f1.y);
        uint2 w;
        w.x = *reinterpret_cast<uint32_t*>(&e0);
        w.y = *reinterpret_cast<uint32_t*>(&e1);
        *(uint2*)(ph + (size_t)(i * 32 + l) * 4) = w;
    }
#pragma unroll
    for (int o = 16; o > 0; o >>= 1) sum += __shfl_xor_sync(0xffffffffu, sum, o);
    if (l == 0) g_l[row] = sum;
}

// ---------------------------------------------------------------------------
extern "C" void kernel_launch(void* const* d_in, const int* in_sizes, int n_in,
                              void* d_out, int out_size)
{
    const float* x  = (const float*)d_in[0];
    const float* Wq = (const float*)d_in[1];
    const float* bq = (const float*)d_in[2];
    const float* Wk = (const float*)d_in[3];
    const float* bk = (const float*)d_in[4];
    const float* Wv = (const float*)d_in[5];
    const float* bv = (const float*)d_in[6];
    float* out = (float*)d_out;

    cudaFuncSetAttribute(gemm3<M_PROJQK, 8>, cudaFuncAttributeMaxDynamicSharedMemorySize, SMEM_SZ);
    cudaFuncSetAttribute(gemm3<M_PROJVT, 8>, cudaFuncAttributeMaxDynamicSharedMemorySize, SMEM_SZ);
    cudaFuncSetAttribute(gemm3<M_QK, 8>,     cudaFuncAttributeMaxDynamicSharedMemorySize, SMEM_SZ);
    cudaFuncSetAttribute(gemm_pv,            cudaFuncAttributeMaxDynamicSharedMemorySize, PV_SMEM);

    // main chain (default stream): prep -> projQK -> QK -> softmax -> PV
    prep<<<16384 + 24, 256>>>(x, Wq, Wk, Wv);

    // fork: projVT on side stream, concurrent with projQK/QK/softmax
    cudaEventRecord(g_e1, 0);
    cudaStreamWaitEvent(g_s1, g_e1, 0);
    gemm3<M_PROJVT, 8><<<dim3(2, 4, 64), 256, SMEM_SZ, g_s1>>>(bq, bk, bv);
    cudaEventRecord(g_e2, g_s1);

    gemm3<M_PROJQK, 8><<<dim3(512, 2),   256, SMEM_SZ>>>(bq, bk, bv);
    gemm3<M_QK, 8>    <<<dim3(8, 4, 64), 256, SMEM_SZ>>>(bq, bk, bv);
    softmax_rows      <<<MTOT / 8, 256>>>();

    // join: PV needs both softmax (default stream) and projVT (side stream)
    cudaStreamWaitEvent(0, g_e2, 0);
    gemm_pv<<<dim3(8, 64), 256, PV_SMEM>>>(out);
}

// round 14
// speedup vs baseline: 1.4879x; 1.0511x over previous
#include <cuda_runtime.h>
#include <cuda_bf16.h>
#include <cuda_fp16.h>
#include <cstdint>

// ---------------------------------------------------------------------------
#define BATCH 64
#define SEQ   1024
#define EDIM  256
#define HDIM  256
#define MTOT  (BATCH * SEQ)       // 65536
#define NCHK  4                   // batch chunks for pipelining
#define BCHK  (BATCH / NCHK)      // 16 batches per chunk

// Pre-split fp16 operands, produced once, consumed by MMA mainloops.
__device__ __half g_xh [(size_t)MTOT * EDIM];
__device__ __half g_xl [(size_t)MTOT * EDIM];
__device__ __half g_qh [(size_t)MTOT * HDIM];
__device__ __half g_ql [(size_t)MTOT * HDIM];
__device__ __half g_kh [(size_t)MTOT * HDIM];
__device__ __half g_kl [(size_t)MTOT * HDIM];
__device__ __half g_vth[(size_t)BATCH * EDIM * SEQ];   // V^T fp16 (single)
__device__ __half g_ph [(size_t)BATCH * SEQ * SEQ];    // P fp16 (UNNORMALIZED)
__device__ float  g_l  [(size_t)MTOT];                 // per-row softmax sums
__device__ float  g_s  [(size_t)BATCH * SEQ * SEQ];    // fp32 logits
__device__ __half g_wqTh[EDIM * HDIM], g_wqTl[EDIM * HDIM];
__device__ __half g_wkTh[EDIM * HDIM], g_wkTl[EDIM * HDIM];
__device__ __half g_wvTh[EDIM * HDIM], g_wvTl[EDIM * HDIM];

// ---------------------------------------------------------------------------
// Host-side streams/events for graph fork + chunk pipelining (host objects).
// ---------------------------------------------------------------------------
static cudaStream_t g_sv, g_sm, g_pv;
static cudaEvent_t  g_e1, g_e2, g_eqk[NCHK], g_esm[NCHK], g_edone;
static struct _StreamInit {
    _StreamInit() {
        cudaStreamCreateWithFlags(&g_sv, cudaStreamNonBlocking);
        cudaStreamCreateWithFlags(&g_sm, cudaStreamNonBlocking);
        cudaStreamCreateWithFlags(&g_pv, cudaStreamNonBlocking);
        cudaEventCreateWithFlags(&g_e1, cudaEventDisableTiming);
        cudaEventCreateWithFlags(&g_e2, cudaEventDisableTiming);
        cudaEventCreateWithFlags(&g_edone, cudaEventDisableTiming);
        for (int i = 0; i < NCHK; i++) {
            cudaEventCreateWithFlags(&g_eqk[i], cudaEventDisableTiming);
            cudaEventCreateWithFlags(&g_esm[i], cudaEventDisableTiming);
        }
    }
} g_stream_init;

// ---------------------------------------------------------------------------
// helpers
// ---------------------------------------------------------------------------
__device__ __forceinline__ uint32_t smem_u32(const void* p) {
    uint32_t a;
    asm("{ .reg .u64 t; cvta.to.shared.u64 t, %1; cvt.u32.u64 %0, t; }" : "=r"(a) : "l"(p));
    return a;
}
__device__ __forceinline__ void ldsm_x4(uint32_t* r, uint32_t addr) {
    asm volatile("ldmatrix.sync.aligned.m8n8.x4.shared.b16 {%0,%1,%2,%3}, [%4];"
                 : "=r"(r[0]), "=r"(r[1]), "=r"(r[2]), "=r"(r[3]) : "r"(addr));
}
__device__ __forceinline__ void mma_f16(float* c, const uint32_t* a, const uint32_t* b) {
    asm volatile(
        "mma.sync.aligned.m16n8k16.row.col.f32.f16.f16.f32 "
        "{%0,%1,%2,%3}, {%4,%5,%6,%7}, {%8,%9}, {%0,%1,%2,%3};"
        : "+f"(c[0]), "+f"(c[1]), "+f"(c[2]), "+f"(c[3])
        : "r"(a[0]), "r"(a[1]), "r"(a[2]), "r"(a[3]), "r"(b[0]), "r"(b[1]));
}
// hi/lo fp16 split of two floats, packed as half2 words
__device__ __forceinline__ void split2h(float x, float y, uint32_t& h, uint32_t& l) {
    __half2 H = __floats2half2_rn(x, y);
    float hx = __half2float(__low2half(H));
    float hy = __half2float(__high2half(H));
    __half2 L = __floats2half2_rn(x - hx, y - hy);
    h = *reinterpret_cast<uint32_t*>(&H);
    l = *reinterpret_cast<uint32_t*>(&L);
}

#define CP16(sm, gp)  asm volatile("cp.async.cg.shared.global [%0], [%1], 16;" :: "r"(sm), "l"(gp))
#define CP_COMMIT()   asm volatile("cp.async.commit_group;" ::: "memory")
#define CP_WAIT1()    asm volatile("cp.async.wait_group 1;" ::: "memory")

// ---------------------------------------------------------------------------
// GEMM: C[128 x 256] = A[128 x K] @ B[256 x K]^T, fp16 hi/lo splits.
// 256 threads, 8 warps (2m x 4n), warp tile 64x64.
// K in chunks of 32; 3-stage cp.async pipeline, ONE __syncthreads per chunk.
//   M_PROJQK: 3-term  (A hi/lo, B hi/lo)   -- precision-critical
//   M_PROJVT: 2-term  (A hi only, B hi/lo)
//   M_QK:     2-term  (A hi/lo, B hi only) -- (ah+al)*bh = a_exact*bh
// ---------------------------------------------------------------------------
#define ROWB   80
#define S_AH   0
#define S_AL   10240                 // 128*80
#define S_BH   20480
#define S_BL   40960                 // + 256*80
#define STAGE_SZ 61440
#define SMEM_SZ  (3 * STAGE_SZ)      // 184320

enum { M_PROJQK = 0, M_PROJVT = 1, M_QK = 2 };

template<int MODE, int NCHUNKK>
__global__ __launch_bounds__(256, 1)
void gemm3(const float* __restrict__ bq, const float* __restrict__ bk,
           const float* __restrict__ bv, int b0)
{
    extern __shared__ __align__(128) char smem[];
    const uint32_t sbase = smem_u32(smem);
    const int t    = threadIdx.x;
    const int lane = t & 31;
    const int wid  = t >> 5;          // 0..7
    const int wm   = wid >> 2;        // 0..1  (64-row slab)
    const int wn   = wid & 3;         // 0..3  (64-col slab)

    constexpr bool USE_ALO = (MODE != M_PROJVT);
    constexpr bool USE_BLO = (MODE != M_QK);

    // ---- operand resolution ----
    const uint16_t *Ah, *Al = nullptr, *Bh, *Bl = nullptr;
    __half *Ch = nullptr, *Cl = nullptr, *Chh = nullptr;
    float* Cf = nullptr;
    const float* bias = nullptr;
    size_t lda, ldb, ldc;

    if (MODE == M_PROJQK) {
        int mt = blockIdx.x, qk = blockIdx.y;
        Ah = (const uint16_t*)(g_xh + (size_t)mt * 128 * EDIM);
        Al = (const uint16_t*)(g_xl + (size_t)mt * 128 * EDIM);                 lda = EDIM;
        Bh = (const uint16_t*)(qk ? g_wkTh : g_wqTh);
        Bl = (const uint16_t*)(qk ? g_wkTl : g_wqTl);                           ldb = EDIM;
        size_t co = (size_t)mt * 128 * HDIM;
        Ch = (qk ? g_kh : g_qh) + co;  Cl = (qk ? g_kl : g_ql) + co;            ldc = HDIM;
        bias = qk ? bk : bq;
    } else if (MODE == M_PROJVT) {
        int mt = blockIdx.x, nt = blockIdx.y, b = blockIdx.z;
        Ah = (const uint16_t*)(g_wvTh + (size_t)mt * 128 * EDIM);               lda = EDIM;
        size_t bo = ((size_t)b * SEQ + nt * 256) * EDIM;
        Bh = (const uint16_t*)(g_xh + bo);  Bl = (const uint16_t*)(g_xl + bo);  ldb = EDIM;
        Chh = g_vth + (size_t)b * EDIM * SEQ + (size_t)mt * 128 * SEQ + nt * 256; ldc = SEQ;
        bias = bv + mt * 128;
    } else {                          // M_QK: 2-term, no B-lo
        int mt = blockIdx.x, nt = blockIdx.y, b = b0 + blockIdx.z;
        size_t ao = ((size_t)b * SEQ + mt * 128) * HDIM;
        size_t bo = ((size_t)b * SEQ + nt * 256) * HDIM;
        Ah = (const uint16_t*)(g_qh + ao); Al = (const uint16_t*)(g_ql + ao);   lda = HDIM;
        Bh = (const uint16_t*)(g_kh + bo);                                      ldb = HDIM;
        Cf = g_s + (size_t)b * SEQ * SEQ + (size_t)mt * 128 * SEQ + nt * 256;   ldc = SEQ;
    }

    float acc[4][8][4];
#pragma unroll
    for (int i = 0; i < 4; i++)
#pragma unroll
        for (int j = 0; j < 8; j++)
#pragma unroll
            for (int e = 0; e < 4; e++) acc[i][j][e] = 0.f;

    // cp.async mapping (256 threads): A 128 rows x 64B, B 256 rows x 64B.
    const int r_ld = t >> 2;             // 0..63
    const int cb16 = (t & 3) << 4;       // smem byte within row
    const int cel  = (t & 3) << 3;       // gmem element offset

#define LOAD_STAGE(J, BUF)                                                     \
    {                                                                          \
        const uint32_t sp = sbase + (uint32_t)(BUF) * STAGE_SZ;                \
        _Pragma("unroll")                                                      \
        for (int i = 0; i < 2; i++) {                                          \
            int r = r_ld + 64 * i;                                             \
            uint32_t so = (uint32_t)(r * ROWB + cb16);                         \
            size_t ga = (size_t)r * lda + (size_t)(J) * 32 + cel;              \
            CP16(sp + S_AH + so, Ah + ga);                                     \
            if (USE_ALO) CP16(sp + S_AL + so, Al + ga);                        \
        }                                                                      \
        _Pragma("unroll")                                                      \
        for (int i = 0; i < 4; i++) {                                          \
            int r = r_ld + 64 * i;                                             \
            uint32_t so = (uint32_t)(r * ROWB + cb16);                         \
            size_t gb = (size_t)r * ldb + (size_t)(J) * 32 + cel;              \
            CP16(sp + S_BH + so, Bh + gb);                                     \
            if (USE_BLO) CP16(sp + S_BL + so, Bl + gb);                        \
        }                                                                      \
    }

    // ldmatrix offsets (within a plane region)
    const uint32_t aoff = (uint32_t)((wm * 64 + (lane & 15)) * ROWB + ((lane >> 4) << 4));
    const uint32_t boff = (uint32_t)((wn * 64 + ((lane >> 4) << 3) + (lane & 7)) * ROWB
                                     + (((lane >> 3) & 1) << 4));

    // prologue: 2 stages in flight
    LOAD_STAGE(0, 0); CP_COMMIT();
    LOAD_STAGE(1, 1); CP_COMMIT();

#pragma unroll 1
    for (int j = 0; j < NCHUNKK; j++) {
        CP_WAIT1();
        __syncthreads();    // single barrier per chunk

        const uint32_t st = sbase + (uint32_t)(j % 3) * STAGE_SZ;
#pragma unroll
        for (int ks = 0; ks < 2; ks++) {
            const uint32_t ko = (uint32_t)(ks * 32);
            uint32_t ah[4][4], al[4][4], b4[4][4];
#pragma unroll
            for (int mf = 0; mf < 4; mf++)
                ldsm_x4(ah[mf], st + S_AH + aoff + (uint32_t)(mf * 16 * ROWB) + ko);
#pragma unroll
            for (int ng = 0; ng < 4; ng++)
                ldsm_x4(b4[ng], st + S_BH + boff + (uint32_t)(ng * 16 * ROWB) + ko);
#pragma unroll
            for (int mf = 0; mf < 4; mf++)
#pragma unroll
                for (int nf = 0; nf < 8; nf++)
                    mma_f16(acc[mf][nf], ah[mf], &b4[nf >> 1][(nf & 1) * 2]);

            if (USE_ALO) {
#pragma unroll
                for (int mf = 0; mf < 4; mf++)
                    ldsm_x4(al[mf], st + S_AL + aoff + (uint32_t)(mf * 16 * ROWB) + ko);
#pragma unroll
                for (int mf = 0; mf < 4; mf++)
#pragma unroll
                    for (int nf = 0; nf < 8; nf++)
                        mma_f16(acc[mf][nf], al[mf], &b4[nf >> 1][(nf & 1) * 2]);
            }
            if (USE_BLO) {
#pragma unroll
                for (int ng = 0; ng < 4; ng++)
                    ldsm_x4(b4[ng], st + S_BL + boff + (uint32_t)(ng * 16 * ROWB) + ko);
#pragma unroll
                for (int mf = 0; mf < 4; mf++)
#pragma unroll
                    for (int nf = 0; nf < 8; nf++)
                        mma_f16(acc[mf][nf], ah[mf], &b4[nf >> 1][(nf & 1) * 2]);
            }

            if (ks == 0) {   // issue next-stage loads between the two k-steps
                if (j + 2 < NCHUNKK) LOAD_STAGE(j + 2, (j + 2) % 3);
                CP_COMMIT();
            }
        }
    }

    // ---- epilogue ----
#pragma unroll
    for (int mf = 0; mf < 4; mf++) {
        const int r0 = wm * 64 + mf * 16 + (lane >> 2);
        const int r1 = r0 + 8;
#pragma unroll
        for (int nf = 0; nf < 8; nf++) {
            const int c = wn * 64 + nf * 8 + ((lane & 3) << 1);
            float* a = acc[mf][nf];
            if (MODE == M_PROJQK) {
                float cb0 = bias[c], cb1 = bias[c + 1];
                uint32_t h, l;
                split2h(a[0] + cb0, a[1] + cb1, h, l);
                *(uint32_t*)(Ch + (size_t)r0 * ldc + c) = h;
                *(uint32_t*)(Cl + (size_t)r0 * ldc + c) = l;
                split2h(a[2] + cb0, a[3] + cb1, h, l);
                *(uint32_t*)(Ch + (size_t)r1 * ldc + c) = h;
                *(uint32_t*)(Cl + (size_t)r1 * ldc + c) = l;
            } else if (MODE == M_PROJVT) {
                float rb0 = bias[r0], rb1 = bias[r1];
                __half2 h0 = __floats2half2_rn(a[0] + rb0, a[1] + rb0);
                __half2 h1 = __floats2half2_rn(a[2] + rb1, a[3] + rb1);
                *(uint32_t*)(Chh + (size_t)r0 * ldc + c) = *reinterpret_cast<uint32_t*>(&h0);
                *(uint32_t*)(Chh + (size_t)r1 * ldc + c) = *reinterpret_cast<uint32_t*>(&h1);
            } else {
                *(float2*)(Cf + (size_t)r0 * ldc + c) = make_float2(a[0], a[1]);
                *(float2*)(Cf + (size_t)r1 * ldc + c) = make_float2(a[2], a[3]);
            }
        }
    }
#undef LOAD_STAGE
}

// ---------------------------------------------------------------------------
// PV: O[128 x 256] = P~[128 x 1024] @ V^T[256 x 1024]^T, 1-term fp16.
// K-chunk 64, 3-stage pipeline, rows 128B padded to 144B. Scales by 1/l.
// ---------------------------------------------------------------------------
#define PVROWB  144
#define PV_SA   0
#define PV_SB   18432                // 128*144
#define PV_STG  55296                // + 256*144
#define PV_SMEM (3 * PV_STG)         // 165888

__global__ __launch_bounds__(256, 1)
void gemm_pv(float* __restrict__ outp, int b0)
{
    extern __shared__ __align__(128) char smem[];
    const uint32_t sbase = smem_u32(smem);
    const int t    = threadIdx.x;
    const int lane = t & 31;
    const int wid  = t >> 5;
    const int wm   = wid >> 2;
    const int wn   = wid & 3;
    const int mt   = blockIdx.x;
    const int b    = b0 + blockIdx.y;

    const uint16_t* Ah = (const uint16_t*)(g_ph + (size_t)b * SEQ * SEQ + (size_t)mt * 128 * SEQ);
    const uint16_t* Bh = (const uint16_t*)(g_vth + (size_t)b * EDIM * SEQ);
    float* Cf = outp + ((size_t)b * SEQ + mt * 128) * EDIM;
    const float* Lp = g_l + (size_t)b * SEQ + mt * 128;

    float acc[4][8][4];
#pragma unroll
    for (int i = 0; i < 4; i++)
#pragma unroll
        for (int j = 0; j < 8; j++)
#pragma unroll
            for (int e = 0; e < 4; e++) acc[i][j][e] = 0.f;

#define PV_LOAD(J, BUF)                                                        \
    {                                                                          \
        const uint32_t sp = sbase + (uint32_t)(BUF) * PV_STG;                  \
        _Pragma("unroll")                                                      \
        for (int i = 0; i < 4; i++) {                                          \
            int idx = t + 256 * i;                                             \
            int r = idx >> 3, c16 = (idx & 7) << 4, ce = (idx & 7) << 3;       \
            CP16(sp + PV_SA + (uint32_t)(r * PVROWB + c16),                    \
                 Ah + (size_t)r * SEQ + (size_t)(J) * 64 + ce);                \
        }                                                                      \
        _Pragma("unroll")                                                      \
        for (int i = 0; i < 8; i++) {                                          \
            int idx = t + 256 * i;                                             \
            int r = idx >> 3, c16 = (idx & 7) << 4, ce = (idx & 7) << 3;       \
            CP16(sp + PV_SB + (uint32_t)(r * PVROWB + c16),                    \
                 Bh + (size_t)r * SEQ + (size_t)(J) * 64 + ce);                \
        }                                                                      \
    }

    const uint32_t aoff = (uint32_t)((wm * 64 + (lane & 15)) * PVROWB + ((lane >> 4) << 4));
    const uint32_t boff = (uint32_t)((wn * 64 + ((lane >> 4) << 3) + (lane & 7)) * PVROWB
                                     + (((lane >> 3) & 1) << 4));

    PV_LOAD(0, 0); CP_COMMIT();
    PV_LOAD(1, 1); CP_COMMIT();

#pragma unroll 1
    for (int j = 0; j < 16; j++) {
        CP_WAIT1();
        __syncthreads();

        const uint32_t st = sbase + (uint32_t)(j % 3) * PV_STG;
#pragma unroll
        for (int ks = 0; ks < 4; ks++) {
            const uint32_t ko = (uint32_t)(ks * 32);
            uint32_t ah[4][4], b4[4][4];
#pragma unroll
            for (int mf = 0; mf < 4; mf++)
                ldsm_x4(ah[mf], st + PV_SA + aoff + (uint32_t)(mf * 16 * PVROWB) + ko);
#pragma unroll
            for (int ng = 0; ng < 4; ng++)
                ldsm_x4(b4[ng], st + PV_SB + boff + (uint32_t)(ng * 16 * PVROWB) + ko);
#pragma unroll
            for (int mf = 0; mf < 4; mf++)
#pragma unroll
                for (int nf = 0; nf < 8; nf++)
                    mma_f16(acc[mf][nf], ah[mf], &b4[nf >> 1][(nf & 1) * 2]);

            if (ks == 0) {
                if (j + 2 < 16) PV_LOAD(j + 2, (j + 2) % 3);
                CP_COMMIT();
            }
        }
    }

#pragma unroll
    for (int mf = 0; mf < 4; mf++) {
        const int r0 = wm * 64 + mf * 16 + (lane >> 2);
        const int r1 = r0 + 8;
        const float inv0 = 1.f / Lp[r0];
        const float inv1 = 1.f / Lp[r1];
#pragma unroll
        for (int nf = 0; nf < 8; nf++) {
            const int c = wn * 64 + nf * 8 + ((lane & 3) << 1);
            float* a = acc[mf][nf];
            *(float2*)(Cf + (size_t)r0 * EDIM + c) = make_float2(a[0] * inv0, a[1] * inv0);
            *(float2*)(Cf + (size_t)r1 * EDIM + c) = make_float2(a[2] * inv1, a[3] * inv1);
        }
    }
#undef PV_LOAD
}

// ---------------------------------------------------------------------------
// Prep (one launch): blocks [0,16384) split x into fp16 hi/lo;
// blocks [16384, 16384+24) transpose+split W (3 matrices x 8 row-slabs).
// ---------------------------------------------------------------------------
__global__ __launch_bounds__(256) void prep(const float* __restrict__ x,
                                            const float* __restrict__ Wq,
                                            const float* __restrict__ Wk,
                                            const float* __restrict__ Wv)
{
    const int bx = blockIdx.x;
    const int t  = threadIdx.x;
    if (bx < 16384) {
        size_t i = ((size_t)bx * 256 + t) * 4;
        float4 v = *(const float4*)(x + i);
        uint32_t h01, l01, h23, l23;
        split2h(v.x, v.y, h01, l01);
        split2h(v.z, v.w, h23, l23);
        *(uint2*)(g_xh + i) = make_uint2(h01, h23);
        *(uint2*)(g_xl + i) = make_uint2(l01, l23);
        return;
    }
    const int r2 = bx - 16384;      // 0..23
    const int m  = r2 >> 3;         // matrix
    const int ti = r2 & 7;          // 32-row slab of src
    const float* src = (m == 0) ? Wq : (m == 1) ? Wk : Wv;
    __half* dh = (m == 0) ? g_wqTh : (m == 1) ? g_wkTh : g_wvTh;
    __half* dl = (m == 0) ? g_wqTl : (m == 1) ? g_wkTl : g_wvTl;
    __shared__ float sm[32 * 33];
    const int w = t >> 5, l = t & 31;
    for (int tj = 0; tj < 8; tj++) {
#pragma unroll
        for (int k = 0; k < 4; k++) {
            int r = w * 4 + k;
            sm[r * 33 + l] = src[(size_t)(ti * 32 + r) * 256 + tj * 32 + l];
        }
        __syncthreads();
#pragma unroll
        for (int k = 0; k < 4; k++) {
            int r = w * 4 + k;
            float v = sm[l * 33 + r];
            __half h = __float2half_rn(v);
            dh[(size_t)(tj * 32 + r) * 256 + ti * 32 + l] = h;
            dl[(size_t)(tj * 32 + r) * 256 + ti * 32 + l] = __float2half_rn(v - __half2float(h));
        }
        __syncthreads();
    }
}

// ---------------------------------------------------------------------------
// Softmax: one warp per row of the batch chunk. Writes UNNORMALIZED
// P~ = exp2((s-m)*log2e) as fp16 via h2exp2, row sum to g_l.
// ---------------------------------------------------------------------------
__global__ __launch_bounds__(256) void softmax_rows(int b0)
{
    const size_t row = (size_t)b0 * SEQ + (size_t)blockIdx.x * 8 + (threadIdx.x >> 5);
    const int l = threadIdx.x & 31;
    const float4* p = (const float4*)(g_s + row * SEQ);

    float4 v[8];
    float mx = -3.4e38f;
#pragma unroll
    for (int i = 0; i < 8; i++) {
        v[i] = p[i * 32 + l];
        mx = fmaxf(mx, fmaxf(fmaxf(v[i].x, v[i].y), fmaxf(v[i].z, v[i].w)));
    }
#pragma unroll
    for (int o = 16; o > 0; o >>= 1) mx = fmaxf(mx, __shfl_xor_sync(0xffffffffu, mx, o));

    const float L2E = 1.4426950408889634f;
    const float mb  = -mx * L2E;
    float sum = 0.f;
    __half* ph = g_ph + row * SEQ;
#pragma unroll
    for (int i = 0; i < 8; i++) {
        __half2 y0 = __floats2half2_rn(fmaf(v[i].x, L2E, mb), fmaf(v[i].y, L2E, mb));
        __half2 y1 = __floats2half2_rn(fmaf(v[i].z, L2E, mb), fmaf(v[i].w, L2E, mb));
        __half2 e0 = h2exp2(y0);
        __half2 e1 = h2exp2(y1);
        float2 f0 = __half22float2(e0);
        float2 f1 = __half22float2(e1);
        sum += (f0.x + f0.y) + (f1.x + f1.y);
        uint2 w;
        w.x = *reinterpret_cast<uint32_t*>(&e0);
        w.y = *reinterpret_cast<uint32_t*>(&e1);
        *(uint2*)(ph + (size_t)(i * 32 + l) * 4) = w;
    }
#pragma unroll
    for (int o = 16; o > 0; o >>= 1) sum += __shfl_xor_sync(0xffffffffu, sum, o);
    if (l == 0) g_l[row] = sum;
}

// ---------------------------------------------------------------------------
extern "C" void kernel_launch(void* const* d_in, const int* in_sizes, int n_in,
                              void* d_out, int out_size)
{
    const float* x  = (const float*)d_in[0];
    const float* Wq = (const float*)d_in[1];
    const float* bq = (const float*)d_in[2];
    const float* Wk = (const float*)d_in[3];
    const float* bk = (const float*)d_in[4];
    const float* Wv = (const float*)d_in[5];
    const float* bv = (const float*)d_in[6];
    float* out = (float*)d_out;

    cudaFuncSetAttribute(gemm3<M_PROJQK, 8>, cudaFuncAttributeMaxDynamicSharedMemorySize, SMEM_SZ);
    cudaFuncSetAttribute(gemm3<M_PROJVT, 8>, cudaFuncAttributeMaxDynamicSharedMemorySize, SMEM_SZ);
    cudaFuncSetAttribute(gemm3<M_QK, 8>,     cudaFuncAttributeMaxDynamicSharedMemorySize, SMEM_SZ);
    cudaFuncSetAttribute(gemm_pv,            cudaFuncAttributeMaxDynamicSharedMemorySize, PV_SMEM);

    // main chain (default stream): prep -> projQK -> QK chunks
    prep<<<16384 + 24, 256>>>(x, Wq, Wk, Wv);

    // fork: projVT on side stream (needed only by PV)
    cudaEventRecord(g_e1, 0);
    cudaStreamWaitEvent(g_sv, g_e1, 0);
    gemm3<M_PROJVT, 8><<<dim3(2, 4, 64), 256, SMEM_SZ, g_sv>>>(bq, bk, bv, 0);
    cudaEventRecord(g_e2, g_sv);
    cudaStreamWaitEvent(g_pv, g_e2, 0);   // PV stream gates on V once

    gemm3<M_PROJQK, 8><<<dim3(512, 2), 256, SMEM_SZ>>>(bq, bk, bv, 0);

    // pipelined chunks: QK on default; softmax on g_sm; PV on g_pv
    for (int c = 0; c < NCHK; c++) {
        const int b0 = c * BCHK;
        gemm3<M_QK, 8><<<dim3(8, 4, BCHK), 256, SMEM_SZ>>>(bq, bk, bv, b0);
        cudaEventRecord(g_eqk[c], 0);

        cudaStreamWaitEvent(g_sm, g_eqk[c], 0);
        softmax_rows<<<BCHK * SEQ / 8, 256, 0, g_sm>>>(b0);
        cudaEventRecord(g_esm[c], g_sm);

        cudaStreamWaitEvent(g_pv, g_esm[c], 0);
        gemm_pv<<<dim3(8, BCHK), 256, PV_SMEM, g_pv>>>(out, b0);
    }

    // join all side work back into the capture-origin stream
    cudaEventRecord(g_edone, g_pv);
    cudaStreamWaitEvent(0, g_edone, 0);
}

// round 15
// speedup vs baseline: 1.4978x; 1.0067x over previous
#include <cuda_runtime.h>
#include <cuda_bf16.h>
#include <cuda_fp16.h>
#include <cstdint>

// ---------------------------------------------------------------------------
#define BATCH 64
#define SEQ   1024
#define EDIM  256
#define HDIM  256
#define MTOT  (BATCH * SEQ)       // 65536
#define NCHK  4                   // batch chunks for pipelining
#define BCHK  (BATCH / NCHK)      // 16 batches per chunk

// Pre-split fp16 operands, produced once, consumed by MMA mainloops.
__device__ __half g_xh [(size_t)MTOT * EDIM];
__device__ __half g_xl [(size_t)MTOT * EDIM];
__device__ __half g_qh [(size_t)MTOT * HDIM];
__device__ __half g_ql [(size_t)MTOT * HDIM];
__device__ __half g_kh [(size_t)MTOT * HDIM];
__device__ __half g_kl [(size_t)MTOT * HDIM];
__device__ __half g_vth[(size_t)BATCH * EDIM * SEQ];   // V^T fp16 (single)
__device__ __half g_ph [(size_t)BATCH * SEQ * SEQ];    // P fp16 (UNNORMALIZED)
__device__ float  g_l  [(size_t)MTOT];                 // per-row softmax sums
__device__ float  g_s  [(size_t)BATCH * SEQ * SEQ];    // fp32 logits
__device__ __half g_wqTh[EDIM * HDIM], g_wqTl[EDIM * HDIM];
__device__ __half g_wkTh[EDIM * HDIM], g_wkTl[EDIM * HDIM];
__device__ __half g_wvTh[EDIM * HDIM], g_wvTl[EDIM * HDIM];

// ---------------------------------------------------------------------------
// Host-side streams/events for graph fork + chunk pipelining (host objects).
// ---------------------------------------------------------------------------
static cudaStream_t g_sv, g_sm, g_pv, g_qk2;
static cudaEvent_t  g_e1, g_e2, g_eproj, g_eqk[NCHK], g_esm[NCHK], g_edone, g_eqkj;
static struct _StreamInit {
    _StreamInit() {
        cudaStreamCreateWithFlags(&g_sv,  cudaStreamNonBlocking);
        cudaStreamCreateWithFlags(&g_sm,  cudaStreamNonBlocking);
        cudaStreamCreateWithFlags(&g_pv,  cudaStreamNonBlocking);
        cudaStreamCreateWithFlags(&g_qk2, cudaStreamNonBlocking);
        cudaEventCreateWithFlags(&g_e1,    cudaEventDisableTiming);
        cudaEventCreateWithFlags(&g_e2,    cudaEventDisableTiming);
        cudaEventCreateWithFlags(&g_eproj, cudaEventDisableTiming);
        cudaEventCreateWithFlags(&g_edone, cudaEventDisableTiming);
        cudaEventCreateWithFlags(&g_eqkj,  cudaEventDisableTiming);
        for (int i = 0; i < NCHK; i++) {
            cudaEventCreateWithFlags(&g_eqk[i], cudaEventDisableTiming);
            cudaEventCreateWithFlags(&g_esm[i], cudaEventDisableTiming);
        }
    }
} g_stream_init;

// ---------------------------------------------------------------------------
// helpers
// ---------------------------------------------------------------------------
__device__ __forceinline__ uint32_t smem_u32(const void* p) {
    uint32_t a;
    asm("{ .reg .u64 t; cvta.to.shared.u64 t, %1; cvt.u32.u64 %0, t; }" : "=r"(a) : "l"(p));
    return a;
}
__device__ __forceinline__ void ldsm_x4(uint32_t* r, uint32_t addr) {
    asm volatile("ldmatrix.sync.aligned.m8n8.x4.shared.b16 {%0,%1,%2,%3}, [%4];"
                 : "=r"(r[0]), "=r"(r[1]), "=r"(r[2]), "=r"(r[3]) : "r"(addr));
}
__device__ __forceinline__ void mma_f16(float* c, const uint32_t* a, const uint32_t* b) {
    asm volatile(
        "mma.sync.aligned.m16n8k16.row.col.f32.f16.f16.f32 "
        "{%0,%1,%2,%3}, {%4,%5,%6,%7}, {%8,%9}, {%0,%1,%2,%3};"
        : "+f"(c[0]), "+f"(c[1]), "+f"(c[2]), "+f"(c[3])
        : "r"(a[0]), "r"(a[1]), "r"(a[2]), "r"(a[3]), "r"(b[0]), "r"(b[1]));
}
// hi/lo fp16 split of two floats, packed as half2 words
__device__ __forceinline__ void split2h(float x, float y, uint32_t& h, uint32_t& l) {
    __half2 H = __floats2half2_rn(x, y);
    float hx = __half2float(__low2half(H));
    float hy = __half2float(__high2half(H));
    __half2 L = __floats2half2_rn(x - hx, y - hy);
    h = *reinterpret_cast<uint32_t*>(&H);
    l = *reinterpret_cast<uint32_t*>(&L);
}

#define CP16(sm, gp)  asm volatile("cp.async.cg.shared.global [%0], [%1], 16;" :: "r"(sm), "l"(gp))
#define CP_COMMIT()   asm volatile("cp.async.commit_group;" ::: "memory")
#define CP_WAIT1()    asm volatile("cp.async.wait_group 1;" ::: "memory")

// ---------------------------------------------------------------------------
// GEMM: C[128 x 256] = A[128 x K] @ B[256 x K]^T, fp16 hi/lo splits.
// 256 threads, 8 warps (2m x 4n), warp tile 64x64.
// K in chunks of 32; 3-stage cp.async pipeline, ONE __syncthreads per chunk.
//   M_PROJQK: 3-term  (A hi/lo, B hi/lo)   -- precision-critical
//   M_PROJVT: 2-term  (A hi only, B hi/lo)
//   M_QK:     2-term  (A hi/lo, B hi only) -- (ah+al)*bh = a_exact*bh
// ---------------------------------------------------------------------------
#define ROWB   80
#define S_AH   0
#define S_AL   10240                 // 128*80
#define S_BH   20480
#define S_BL   40960                 // + 256*80
#define STAGE_SZ 61440
#define SMEM_SZ  (3 * STAGE_SZ)      // 184320

enum { M_PROJQK = 0, M_PROJVT = 1, M_QK = 2 };

template<int MODE, int NCHUNKK>
__global__ __launch_bounds__(256, 1)
void gemm3(const float* __restrict__ bq, const float* __restrict__ bk,
           const float* __restrict__ bv, int b0)
{
    extern __shared__ __align__(128) char smem[];
    const uint32_t sbase = smem_u32(smem);
    const int t    = threadIdx.x;
    const int lane = t & 31;
    const int wid  = t >> 5;          // 0..7
    const int wm   = wid >> 2;        // 0..1  (64-row slab)
    const int wn   = wid & 3;         // 0..3  (64-col slab)

    constexpr bool USE_ALO = (MODE != M_PROJVT);
    constexpr bool USE_BLO = (MODE != M_QK);

    // ---- operand resolution ----
    const uint16_t *Ah, *Al = nullptr, *Bh, *Bl = nullptr;
    __half *Ch = nullptr, *Cl = nullptr, *Chh = nullptr;
    float* Cf = nullptr;
    const float* bias = nullptr;
    size_t lda, ldb, ldc;

    if (MODE == M_PROJQK) {
        int mt = blockIdx.x, qk = blockIdx.y;
        Ah = (const uint16_t*)(g_xh + (size_t)mt * 128 * EDIM);
        Al = (const uint16_t*)(g_xl + (size_t)mt * 128 * EDIM);                 lda = EDIM;
        Bh = (const uint16_t*)(qk ? g_wkTh : g_wqTh);
        Bl = (const uint16_t*)(qk ? g_wkTl : g_wqTl);                           ldb = EDIM;
        size_t co = (size_t)mt * 128 * HDIM;
        Ch = (qk ? g_kh : g_qh) + co;  Cl = (qk ? g_kl : g_ql) + co;            ldc = HDIM;
        bias = qk ? bk : bq;
    } else if (MODE == M_PROJVT) {
        int mt = blockIdx.x, nt = blockIdx.y, b = blockIdx.z;
        Ah = (const uint16_t*)(g_wvTh + (size_t)mt * 128 * EDIM);               lda = EDIM;
        size_t bo = ((size_t)b * SEQ + nt * 256) * EDIM;
        Bh = (const uint16_t*)(g_xh + bo);  Bl = (const uint16_t*)(g_xl + bo);  ldb = EDIM;
        Chh = g_vth + (size_t)b * EDIM * SEQ + (size_t)mt * 128 * SEQ + nt * 256; ldc = SEQ;
        bias = bv + mt * 128;
    } else {                          // M_QK: 2-term, no B-lo
        int mt = blockIdx.x, nt = blockIdx.y, b = b0 + blockIdx.z;
        size_t ao = ((size_t)b * SEQ + mt * 128) * HDIM;
        size_t bo = ((size_t)b * SEQ + nt * 256) * HDIM;
        Ah = (const uint16_t*)(g_qh + ao); Al = (const uint16_t*)(g_ql + ao);   lda = HDIM;
        Bh = (const uint16_t*)(g_kh + bo);                                      ldb = HDIM;
        Cf = g_s + (size_t)b * SEQ * SEQ + (size_t)mt * 128 * SEQ + nt * 256;   ldc = SEQ;
    }

    float acc[4][8][4];
#pragma unroll
    for (int i = 0; i < 4; i++)
#pragma unroll
        for (int j = 0; j < 8; j++)
#pragma unroll
            for (int e = 0; e < 4; e++) acc[i][j][e] = 0.f;

    // cp.async mapping (256 threads): A 128 rows x 64B, B 256 rows x 64B.
    const int r_ld = t >> 2;             // 0..63
    const int cb16 = (t & 3) << 4;       // smem byte within row
    const int cel  = (t & 3) << 3;       // gmem element offset

#define LOAD_STAGE(J, BUF)                                                     \
    {                                                                          \
        const uint32_t sp = sbase + (uint32_t)(BUF) * STAGE_SZ;                \
        _Pragma("unroll")                                                      \
        for (int i = 0; i < 2; i++) {                                          \
            int r = r_ld + 64 * i;                                             \
            uint32_t so = (uint32_t)(r * ROWB + cb16);                         \
            size_t ga = (size_t)r * lda + (size_t)(J) * 32 + cel;              \
            CP16(sp + S_AH + so, Ah + ga);                                     \
            if (USE_ALO) CP16(sp + S_AL + so, Al + ga);                        \
        }                                                                      \
        _Pragma("unroll")                                                      \
        for (int i = 0; i < 4; i++) {                                          \
            int r = r_ld + 64 * i;                                             \
            uint32_t so = (uint32_t)(r * ROWB + cb16);                         \
            size_t gb = (size_t)r * ldb + (size_t)(J) * 32 + cel;              \
            CP16(sp + S_BH + so, Bh + gb);                                     \
            if (USE_BLO) CP16(sp + S_BL + so, Bl + gb);                        \
        }                                                                      \
    }

    // ldmatrix offsets (within a plane region)
    const uint32_t aoff = (uint32_t)((wm * 64 + (lane & 15)) * ROWB + ((lane >> 4) << 4));
    const uint32_t boff = (uint32_t)((wn * 64 + ((lane >> 4) << 3) + (lane & 7)) * ROWB
                                     + (((lane >> 3) & 1) << 4));

    // prologue: 2 stages in flight
    LOAD_STAGE(0, 0); CP_COMMIT();
    LOAD_STAGE(1, 1); CP_COMMIT();

#pragma unroll 1
    for (int j = 0; j < NCHUNKK; j++) {
        CP_WAIT1();
        __syncthreads();    // single barrier per chunk

        const uint32_t st = sbase + (uint32_t)(j % 3) * STAGE_SZ;
#pragma unroll
        for (int ks = 0; ks < 2; ks++) {
            const uint32_t ko = (uint32_t)(ks * 32);
            uint32_t ah[4][4], al[4][4], b4[4][4];
#pragma unroll
            for (int mf = 0; mf < 4; mf++)
                ldsm_x4(ah[mf], st + S_AH + aoff + (uint32_t)(mf * 16 * ROWB) + ko);
#pragma unroll
            for (int ng = 0; ng < 4; ng++)
                ldsm_x4(b4[ng], st + S_BH + boff + (uint32_t)(ng * 16 * ROWB) + ko);
#pragma unroll
            for (int mf = 0; mf < 4; mf++)
#pragma unroll
                for (int nf = 0; nf < 8; nf++)
                    mma_f16(acc[mf][nf], ah[mf], &b4[nf >> 1][(nf & 1) * 2]);

            if (USE_ALO) {
#pragma unroll
                for (int mf = 0; mf < 4; mf++)
                    ldsm_x4(al[mf], st + S_AL + aoff + (uint32_t)(mf * 16 * ROWB) + ko);
#pragma unroll
                for (int mf = 0; mf < 4; mf++)
#pragma unroll
                    for (int nf = 0; nf < 8; nf++)
                        mma_f16(acc[mf][nf], al[mf], &b4[nf >> 1][(nf & 1) * 2]);
            }
            if (USE_BLO) {
#pragma unroll
                for (int ng = 0; ng < 4; ng++)
                    ldsm_x4(b4[ng], st + S_BL + boff + (uint32_t)(ng * 16 * ROWB) + ko);
#pragma unroll
                for (int mf = 0; mf < 4; mf++)
#pragma unroll
                    for (int nf = 0; nf < 8; nf++)
                        mma_f16(acc[mf][nf], ah[mf], &b4[nf >> 1][(nf & 1) * 2]);
            }

            if (ks == 0) {   // issue next-stage loads between the two k-steps
                if (j + 2 < NCHUNKK) LOAD_STAGE(j + 2, (j + 2) % 3);
                CP_COMMIT();
            }
        }
    }

    // ---- epilogue ----
#pragma unroll
    for (int mf = 0; mf < 4; mf++) {
        const int r0 = wm * 64 + mf * 16 + (lane >> 2);
        const int r1 = r0 + 8;
#pragma unroll
        for (int nf = 0; nf < 8; nf++) {
            const int c = wn * 64 + nf * 8 + ((lane & 3) << 1);
            float* a = acc[mf][nf];
            if (MODE == M_PROJQK) {
                float cb0 = bias[c], cb1 = bias[c + 1];
                uint32_t h, l;
                split2h(a[0] + cb0, a[1] + cb1, h, l);
                *(uint32_t*)(Ch + (size_t)r0 * ldc + c) = h;
                *(uint32_t*)(Cl + (size_t)r0 * ldc + c) = l;
                split2h(a[2] + cb0, a[3] + cb1, h, l);
                *(uint32_t*)(Ch + (size_t)r1 * ldc + c) = h;
                *(uint32_t*)(Cl + (size_t)r1 * ldc + c) = l;
            } else if (MODE == M_PROJVT) {
                float rb0 = bias[r0], rb1 = bias[r1];
                __half2 h0 = __floats2half2_rn(a[0] + rb0, a[1] + rb0);
                __half2 h1 = __floats2half2_rn(a[2] + rb1, a[3] + rb1);
                *(uint32_t*)(Chh + (size_t)r0 * ldc + c) = *reinterpret_cast<uint32_t*>(&h0);
                *(uint32_t*)(Chh + (size_t)r1 * ldc + c) = *reinterpret_cast<uint32_t*>(&h1);
            } else {
                *(float2*)(Cf + (size_t)r0 * ldc + c) = make_float2(a[0], a[1]);
                *(float2*)(Cf + (size_t)r1 * ldc + c) = make_float2(a[2], a[3]);
            }
        }
    }
#undef LOAD_STAGE
}

// ---------------------------------------------------------------------------
// PV: O[128 x 256] = P~[128 x 1024] @ V^T[256 x 1024]^T, 1-term fp16.
// K-chunk 64, 3-stage pipeline, rows 128B padded to 144B. Scales by 1/l.
// ---------------------------------------------------------------------------
#define PVROWB  144
#define PV_SA   0
#define PV_SB   18432                // 128*144
#define PV_STG  55296                // + 256*144
#define PV_SMEM (3 * PV_STG)         // 165888

__global__ __launch_bounds__(256, 1)
void gemm_pv(float* __restrict__ outp, int b0)
{
    extern __shared__ __align__(128) char smem[];
    const uint32_t sbase = smem_u32(smem);
    const int t    = threadIdx.x;
    const int lane = t & 31;
    const int wid  = t >> 5;
    const int wm   = wid >> 2;
    const int wn   = wid & 3;
    const int mt   = blockIdx.x;
    const int b    = b0 + blockIdx.y;

    const uint16_t* Ah = (const uint16_t*)(g_ph + (size_t)b * SEQ * SEQ + (size_t)mt * 128 * SEQ);
    const uint16_t* Bh = (const uint16_t*)(g_vth + (size_t)b * EDIM * SEQ);
    float* Cf = outp + ((size_t)b * SEQ + mt * 128) * EDIM;
    const float* Lp = g_l + (size_t)b * SEQ + mt * 128;

    float acc[4][8][4];
#pragma unroll
    for (int i = 0; i < 4; i++)
#pragma unroll
        for (int j = 0; j < 8; j++)
#pragma unroll
            for (int e = 0; e < 4; e++) acc[i][j][e] = 0.f;

#define PV_LOAD(J, BUF)                                                        \
    {                                                                          \
        const uint32_t sp = sbase + (uint32_t)(BUF) * PV_STG;                  \
        _Pragma("unroll")                                                      \
        for (int i = 0; i < 4; i++) {                                          \
            int idx = t + 256 * i;                                             \
            int r = idx >> 3, c16 = (idx & 7) << 4, ce = (idx & 7) << 3;       \
            CP16(sp + PV_SA + (uint32_t)(r * PVROWB + c16),                    \
                 Ah + (size_t)r * SEQ + (size_t)(J) * 64 + ce);                \
        }                                                                      \
        _Pragma("unroll")                                                      \
        for (int i = 0; i < 8; i++) {                                          \
            int idx = t + 256 * i;                                             \
            int r = idx >> 3, c16 = (idx & 7) << 4, ce = (idx & 7) << 3;       \
            CP16(sp + PV_SB + (uint32_t)(r * PVROWB + c16),                    \
                 Bh + (size_t)r * SEQ + (size_t)(J) * 64 + ce);                \
        }                                                                      \
    }

    const uint32_t aoff = (uint32_t)((wm * 64 + (lane & 15)) * PVROWB + ((lane >> 4) << 4));
    const uint32_t boff = (uint32_t)((wn * 64 + ((lane >> 4) << 3) + (lane & 7)) * PVROWB
                                     + (((lane >> 3) & 1) << 4));

    PV_LOAD(0, 0); CP_COMMIT();
    PV_LOAD(1, 1); CP_COMMIT();

#pragma unroll 1
    for (int j = 0; j < 16; j++) {
        CP_WAIT1();
        __syncthreads();

        const uint32_t st = sbase + (uint32_t)(j % 3) * PV_STG;
#pragma unroll
        for (int ks = 0; ks < 4; ks++) {
            const uint32_t ko = (uint32_t)(ks * 32);
            uint32_t ah[4][4], b4[4][4];
#pragma unroll
            for (int mf = 0; mf < 4; mf++)
                ldsm_x4(ah[mf], st + PV_SA + aoff + (uint32_t)(mf * 16 * PVROWB) + ko);
#pragma unroll
            for (int ng = 0; ng < 4; ng++)
                ldsm_x4(b4[ng], st + PV_SB + boff + (uint32_t)(ng * 16 * PVROWB) + ko);
#pragma unroll
            for (int mf = 0; mf < 4; mf++)
#pragma unroll
                for (int nf = 0; nf < 8; nf++)
                    mma_f16(acc[mf][nf], ah[mf], &b4[nf >> 1][(nf & 1) * 2]);

            if (ks == 0) {
                if (j + 2 < 16) PV_LOAD(j + 2, (j + 2) % 3);
                CP_COMMIT();
            }
        }
    }

#pragma unroll
    for (int mf = 0; mf < 4; mf++) {
        const int r0 = wm * 64 + mf * 16 + (lane >> 2);
        const int r1 = r0 + 8;
        const float inv0 = 1.f / Lp[r0];
        const float inv1 = 1.f / Lp[r1];
#pragma unroll
        for (int nf = 0; nf < 8; nf++) {
            const int c = wn * 64 + nf * 8 + ((lane & 3) << 1);
            float* a = acc[mf][nf];
            *(float2*)(Cf + (size_t)r0 * EDIM + c) = make_float2(a[0] * inv0, a[1] * inv0);
            *(float2*)(Cf + (size_t)r1 * EDIM + c) = make_float2(a[2] * inv1, a[3] * inv1);
        }
    }
#undef PV_LOAD
}

// ---------------------------------------------------------------------------
// Prep (one launch): blocks [0,16384) split x into fp16 hi/lo;
// blocks [16384, 16384+24) transpose+split W (3 matrices x 8 row-slabs).
// ---------------------------------------------------------------------------
__global__ __launch_bounds__(256) void prep(const float* __restrict__ x,
                                            const float* __restrict__ Wq,
                                            const float* __restrict__ Wk,
                                            const float* __restrict__ Wv)
{
    const int bx = blockIdx.x;
    const int t  = threadIdx.x;
    if (bx < 16384) {
        size_t i = ((size_t)bx * 256 + t) * 4;
        float4 v = *(const float4*)(x + i);
        uint32_t h01, l01, h23, l23;
        split2h(v.x, v.y, h01, l01);
        split2h(v.z, v.w, h23, l23);
        *(uint2*)(g_xh + i) = make_uint2(h01, h23);
        *(uint2*)(g_xl + i) = make_uint2(l01, l23);
        return;
    }
    const int r2 = bx - 16384;      // 0..23
    const int m  = r2 >> 3;         // matrix
    const int ti = r2 & 7;          // 32-row slab of src
    const float* src = (m == 0) ? Wq : (m == 1) ? Wk : Wv;
    __half* dh = (m == 0) ? g_wqTh : (m == 1) ? g_wkTh : g_wvTh;
    __half* dl = (m == 0) ? g_wqTl : (m == 1) ? g_wkTl : g_wvTl;
    __shared__ float sm[32 * 33];
    const int w = t >> 5, l = t & 31;
    for (int tj = 0; tj < 8; tj++) {
#pragma unroll
        for (int k = 0; k < 4; k++) {
            int r = w * 4 + k;
            sm[r * 33 + l] = src[(size_t)(ti * 32 + r) * 256 + tj * 32 + l];
        }
        __syncthreads();
#pragma unroll
        for (int k = 0; k < 4; k++) {
            int r = w * 4 + k;
            float v = sm[l * 33 + r];
            __half h = __float2half_rn(v);
            dh[(size_t)(tj * 32 + r) * 256 + ti * 32 + l] = h;
            dl[(size_t)(tj * 32 + r) * 256 + ti * 32 + l] = __float2half_rn(v - __half2float(h));
        }
        __syncthreads();
    }
}

// ---------------------------------------------------------------------------
// Softmax: one warp per row of the batch chunk. Writes UNNORMALIZED
// P~ = exp2((s-m)*log2e) as fp16 via h2exp2, row sum to g_l.
// ---------------------------------------------------------------------------
__global__ __launch_bounds__(256) void softmax_rows(int b0)
{
    const size_t row = (size_t)b0 * SEQ + (size_t)blockIdx.x * 8 + (threadIdx.x >> 5);
    const int l = threadIdx.x & 31;
    const float4* p = (const float4*)(g_s + row * SEQ);

    float4 v[8];
    float mx = -3.4e38f;
#pragma unroll
    for (int i = 0; i < 8; i++) {
        v[i] = p[i * 32 + l];
        mx = fmaxf(mx, fmaxf(fmaxf(v[i].x, v[i].y), fmaxf(v[i].z, v[i].w)));
    }
#pragma unroll
    for (int o = 16; o > 0; o >>= 1) mx = fmaxf(mx, __shfl_xor_sync(0xffffffffu, mx, o));

    const float L2E = 1.4426950408889634f;
    const float mb  = -mx * L2E;
    float sum = 0.f;
    __half* ph = g_ph + row * SEQ;
#pragma unroll
    for (int i = 0; i < 8; i++) {
        __half2 y0 = __floats2half2_rn(fmaf(v[i].x, L2E, mb), fmaf(v[i].y, L2E, mb));
        __half2 y1 = __floats2half2_rn(fmaf(v[i].z, L2E, mb), fmaf(v[i].w, L2E, mb));
        __half2 e0 = h2exp2(y0);
        __half2 e1 = h2exp2(y1);
        float2 f0 = __half22float2(e0);
        float2 f1 = __half22float2(e1);
        sum += (f0.x + f0.y) + (f1.x + f1.y);
        uint2 w;
        w.x = *reinterpret_cast<uint32_t*>(&e0);
        w.y = *reinterpret_cast<uint32_t*>(&e1);
        *(uint2*)(ph + (size_t)(i * 32 + l) * 4) = w;
    }
#pragma unroll
    for (int o = 16; o > 0; o >>= 1) sum += __shfl_xor_sync(0xffffffffu, sum, o);
    if (l == 0) g_l[row] = sum;
}

// ---------------------------------------------------------------------------
extern "C" void kernel_launch(void* const* d_in, const int* in_sizes, int n_in,
                              void* d_out, int out_size)
{
    const float* x  = (const float*)d_in[0];
    const float* Wq = (const float*)d_in[1];
    const float* bq = (const float*)d_in[2];
    const float* Wk = (const float*)d_in[3];
    const float* bk = (const float*)d_in[4];
    const float* Wv = (const float*)d_in[5];
    const float* bv = (const float*)d_in[6];
    float* out = (float*)d_out;

    cudaFuncSetAttribute(gemm3<M_PROJQK, 8>, cudaFuncAttributeMaxDynamicSharedMemorySize, SMEM_SZ);
    cudaFuncSetAttribute(gemm3<M_PROJVT, 8>, cudaFuncAttributeMaxDynamicSharedMemorySize, SMEM_SZ);
    cudaFuncSetAttribute(gemm3<M_QK, 8>,     cudaFuncAttributeMaxDynamicSharedMemorySize, SMEM_SZ);
    cudaFuncSetAttribute(gemm_pv,            cudaFuncAttributeMaxDynamicSharedMemorySize, PV_SMEM);

    // main chain (default stream): prep -> projQK
    prep<<<16384 + 24, 256>>>(x, Wq, Wk, Wv);

    // fork: projVT on side stream (needed only by PV)
    cudaEventRecord(g_e1, 0);
    cudaStreamWaitEvent(g_sv, g_e1, 0);
    gemm3<M_PROJVT, 8><<<dim3(2, 4, 64), 256, SMEM_SZ, g_sv>>>(bq, bk, bv, 0);
    cudaEventRecord(g_e2, g_sv);
    cudaStreamWaitEvent(g_pv, g_e2, 0);   // PV stream gates on V once

    gemm3<M_PROJQK, 8><<<dim3(512, 2), 256, SMEM_SZ>>>(bq, bk, bv, 0);
    cudaEventRecord(g_eproj, 0);
    cudaStreamWaitEvent(g_qk2, g_eproj, 0);   // second QK stream gates on projQK

    // pipelined chunks: QK alternates default / g_qk2 (tails overlap);
    // softmax on g_sm; PV on g_pv.
    for (int c = 0; c < NCHK; c++) {
        const int b0 = c * BCHK;
        cudaStream_t qs = (c & 1) ? g_qk2 : (cudaStream_t)0;
        gemm3<M_QK, 8><<<dim3(8, 4, BCHK), 256, SMEM_SZ, qs>>>(bq, bk, bv, b0);
        cudaEventRecord(g_eqk[c], qs);

        cudaStreamWaitEvent(g_sm, g_eqk[c], 0);
        softmax_rows<<<BCHK * SEQ / 8, 256, 0, g_sm>>>(b0);
        cudaEventRecord(g_esm[c], g_sm);

        cudaStreamWaitEvent(g_pv, g_esm[c], 0);
        gemm_pv<<<dim3(8, BCHK), 256, PV_SMEM, g_pv>>>(out, b0);
    }

    // join all side work back into the capture-origin stream
    cudaEventRecord(g_eqkj, g_qk2);
    cudaStreamWaitEvent(0, g_eqkj, 0);
    cudaEventRecord(g_edone, g_pv);
    cudaStreamWaitEvent(0, g_edone, 0);
}